// round 13
// baseline (speedup 1.0000x reference)
#include <cuda_runtime.h>
#include <cuda_bf16.h>
#include <cuda_fp16.h>
#include <cstdint>
#include <math.h>

#define BB 4
#define LL 512
#define DD 768
#define HH 12
#define MM 48
#define EE 32
#define PP 512
#define RR 97
#define NBK 12
#define NCH 48
#define KCLAS 49152
#define WT_U2 1792
#define WPAD 452
#define WPACK (DD*DD/2)

// ---------------- scratch ----------------
__device__ float g_att_sum[BB*LL*LL];
__device__ float g_mention[BB*MM*DD];
__device__ float g_tmp1[BB*MM*LL];
__device__ float g_eatt[BB*EE*MM];
__device__ float g_emtok[BB*EE*LL];
__device__ float g_entatt[BB*HH*EE*LL];
__device__ float g_hatt[BB*PP*MM];
__device__ float g_tatt[BB*PP*MM];
__device__ uint32_t g_ctxH2[BB*PP*LL/2];
__device__ uint32_t g_ctxL2[BB*PP*LL/2];
__device__ uint32_t g_hH2[BB*PP*DD/2];
__device__ uint32_t g_hL2[BB*PP*DD/2];
__device__ uint32_t g_tH2[BB*PP*DD/2];
__device__ uint32_t g_tL2[BB*PP*DD/2];
__device__ uint32_t g_cinfoH2[BB*PP*DD/2];
__device__ uint32_t g_cinfoL2[BB*PP*DD/2];
__device__ float g_hf[BB*PP*DD];
__device__ float g_tf[BB*PP*DD];
__device__ float g_part[NCH*BB*PP*RR];
__device__ uint32_t g_hWf[WPACK];
__device__ uint32_t g_tWf[WPACK];
__device__ uint32_t g_hcWf[WPACK];
__device__ uint32_t g_tcWf[WPACK];
__device__ uint32_t g_ctxtH2[BB*DD*LL/2];
__device__ uint32_t g_ctxtL2[BB*DD*LL/2];
__device__ uint2 g_Wt[NBK*64*WT_U2];

// ---------------- bf16 helpers ----------------
static __device__ __forceinline__ uint32_t pk2(float e0, float e1) {
    uint32_t r;
    asm("cvt.rn.bf16x2.f32 %0, %1, %2;" : "=r"(r) : "f"(e1), "f"(e0));
    return r;
}
static __device__ __forceinline__ void splitbf(float e0, float e1,
                                               uint32_t& H, uint32_t& L) {
    H = pk2(e0, e1);
    float h0 = __uint_as_float(H << 16);
    float h1 = __uint_as_float(H & 0xffff0000u);
    L = pk2(e0 - h0, e1 - h1);
}
static __device__ __forceinline__ void mma_bf(float* c, const uint32_t* a,
                                              uint32_t b0, uint32_t b1) {
    asm volatile(
        "mma.sync.aligned.m16n8k16.row.col.f32.bf16.bf16.f32 "
        "{%0,%1,%2,%3}, {%4,%5,%6,%7}, {%8,%9}, {%0,%1,%2,%3};"
        : "+f"(c[0]), "+f"(c[1]), "+f"(c[2]), "+f"(c[3])
        : "r"(a[0]), "r"(a[1]), "r"(a[2]), "r"(a[3]), "r"(b0), "r"(b1));
}

// ---------------- fp16 helpers ----------------
static __device__ __forceinline__ uint32_t pkh2(float e0, float e1) {
    __half2 h = __floats2half2_rn(e0, e1);
    return *(uint32_t*)&h;
}
static __device__ __forceinline__ void splitfp16(float e0, float e1,
                                                 uint32_t& H, uint32_t& L) {
    __half2 h = __floats2half2_rn(e0, e1);
    float2 hf = __half22float2(h);
    __half2 l = __floats2half2_rn(e0 - hf.x, e1 - hf.y);
    H = *(uint32_t*)&h;
    L = *(uint32_t*)&l;
}
static __device__ __forceinline__ void mma_fp16(float* c, const uint32_t* a,
                                                uint32_t b0, uint32_t b1) {
    asm volatile(
        "mma.sync.aligned.m16n8k16.row.col.f32.f16.f16.f32 "
        "{%0,%1,%2,%3}, {%4,%5,%6,%7}, {%8,%9}, {%0,%1,%2,%3};"
        : "+f"(c[0]), "+f"(c[1]), "+f"(c[2]), "+f"(c[3])
        : "r"(a[0]), "r"(a[1]), "r"(a[2]), "r"(a[3]), "r"(b0), "r"(b1));
}

// ---------------- merged preprocessing + att_sum (no clasW region) ----------
// regions: [0,1024) att_sum f4 | [1024,5632) weight fp16 pack |
//          [5632,8704) ctxt bf16 split
__global__ void prep_k(const float* __restrict__ att, float* __restrict__ att_sum,
                       const float* __restrict__ hW, const float* __restrict__ tW,
                       const float* __restrict__ hcW, const float* __restrict__ tcW,
                       uint32_t* __restrict__ hWf, uint32_t* __restrict__ tWf,
                       uint32_t* __restrict__ hcWf, uint32_t* __restrict__ tcWf,
                       const float* __restrict__ context,
                       uint32_t* __restrict__ ctH, uint32_t* __restrict__ ctL)
{
    int blk = blockIdx.x, tid = threadIdx.x;
    if (blk < 1024) {
        int idx = blk * 256 + tid;
        int b  = idx >> 16;
        int lm = idx & (LL*LL/4 - 1);
        const float4* p = (const float4*)(att + (size_t)b*HH*LL*LL) + lm;
        float4 s = make_float4(0.f, 0.f, 0.f, 0.f);
#pragma unroll
        for (int h = 0; h < HH; ++h) {
            float4 v = p[(size_t)h*(LL*LL/4)];
            s.x += v.x; s.y += v.y; s.z += v.z; s.w += v.w;
        }
        ((float4*)att_sum)[idx] = s;
    } else if (blk < 5632) {
        int idx = (blk - 1024) * 256 + tid;
        int w = idx / WPACK, j = idx % WPACK;
        const float* src = (w == 0) ? hW : (w == 1) ? tW : (w == 2) ? hcW : tcW;
        uint32_t* dst = (w == 0) ? hWf : (w == 1) ? tWf : (w == 2) ? hcWf : tcWf;
        float2 v = ((const float2*)src)[j];
        dst[j] = pkh2(v.x, v.y);
    } else {
        int idx = (blk - 5632) * 256 + tid;
        int lp = idx & 255;
        int bd = idx >> 8;
        int d = bd % DD, b = bd / DD;
        float e0 = context[((size_t)b*LL + 2*lp)     * DD + d];
        float e1 = context[((size_t)b*LL + 2*lp + 1) * DD + d];
        uint32_t h, l; splitbf(e0, e1, h, l);
        ctH[idx] = h; ctL[idx] = l;
    }
}

// clasW transform: block per (n,i); coalesced load -> smem -> fragment scatter
__global__ __launch_bounds__(256)
void wtrans2_k(const float* __restrict__ W, uint2* __restrict__ Wt)
{
    __shared__ float ww[97*65];
    int ni = blockIdx.x;             // 0..767
    int i = ni & 63, n = ni >> 6;
    int tid = threadIdx.x;
    const float* base = W + (size_t)n*4096 + i*64;
    for (int v = tid; v < 97*64; v += 256) {
        int r = v >> 6, j = v & 63;
        ww[r*65 + j] = base[(size_t)r*KCLAS + j];
    }
    __syncthreads();
    size_t obase = (size_t)ni * WT_U2;
    for (int fi = tid; fi < WT_U2; fi += 256) {
        int r  = fi % 112;
        int s  = (fi / 112) & 3;
        int kq = fi / 448;
        int j0 = s*16 + 2*kq;
        float w00 = 0.f, w01 = 0.f, w10 = 0.f, w11 = 0.f;
        if (r < RR) {
            w00 = ww[r*65 + j0];     w01 = ww[r*65 + j0 + 1];
            w10 = ww[r*65 + j0 + 8]; w11 = ww[r*65 + j0 + 9];
        }
        uint2 o;
        o.x = pkh2(w00, w01);
        o.y = pkh2(w10, w11);
        Wt[obase + fi] = o;
    }
}

// ---------------- small kernels ----------------
__global__ void rownorm_k(float* __restrict__ x)
{
    int row = blockIdx.x;
    float* p = x + (size_t)row * LL;
    int t = threadIdx.x;
    float v0 = p[t], v1 = p[t + 256];
    __shared__ float sm[256];
    sm[t] = v0 + v1; __syncthreads();
    for (int o = 128; o > 0; o >>= 1) { if (t < o) sm[t] += sm[t + o]; __syncthreads(); }
    float inv = 1.f / (sm[0] + 1e-30f);
    p[t] = v0 * inv; p[t + 256] = v1 * inv;
}

// fused mention_att + entity_att: grid=BB, 1024 threads
__global__ __launch_bounds__(1024)
void matteatt_k(const float* __restrict__ tmp1, const float* __restrict__ mmap,
                const float* __restrict__ emap, float* __restrict__ eatt)
{
    __shared__ float ms[MM][MM + 1];
    int b = blockIdx.x;
    int tid = threadIdx.x, wid = tid >> 5, lane = tid & 31;

    for (int o = wid; o < MM*MM; o += 32) {
        int m = o / MM, j = o % MM;
        const float4* a = (const float4*)(tmp1 + ((size_t)b*MM + m)*LL);
        const float4* c = (const float4*)(mmap + ((size_t)b*MM + j)*LL);
        float s = 0.f;
#pragma unroll
        for (int k = lane; k < 128; k += 32) {
            float4 x = a[k], y = c[k];
            s += x.x*y.x + x.y*y.y + x.z*y.z + x.w*y.w;
        }
#pragma unroll
        for (int off = 16; off; off >>= 1) s += __shfl_xor_sync(0xffffffffu, s, off);
        if (lane == 0) ms[m][j] = s;
    }
    __syncthreads();
    for (int v = tid; v < EE*MM; v += 1024) {
        int e = v / MM, j = v % MM;
        float s = 0.f;
#pragma unroll
        for (int m = 0; m < MM; ++m)
            s += emap[((size_t)b*EE + e)*MM + m] * ms[m][j];
        eatt[(size_t)b*EE*MM + v] = s;
    }
}

// ctx_att + pair_att merged (independent outputs, shared hts)
__global__ void ctxpair_k(const int* __restrict__ hts,
                          const float* __restrict__ entatt,
                          const float* __restrict__ emap,
                          const float* __restrict__ eatt,
                          uint32_t* __restrict__ ctxH2, uint32_t* __restrict__ ctxL2,
                          float* __restrict__ hattO, float* __restrict__ tattO)
{
    int bp = blockIdx.x; int b = bp >> 9;
    int hi = hts[(size_t)bp*2], ti = hts[(size_t)bp*2 + 1];
    float mask = (hi + ti != 0) ? 1.f : 0.f;
    int t = threadIdx.x;
    const float* base = entatt + (size_t)b*HH*EE*LL;
    float v0 = 0.f, v1 = 0.f;
#pragma unroll
    for (int h = 0; h < HH; ++h) {
        const float2* ph = (const float2*)(base + ((size_t)h*EE + hi)*LL);
        const float2* pt = (const float2*)(base + ((size_t)h*EE + ti)*LL);
        float2 x = ph[t], y = pt[t];
        v0 += x.x * y.x;
        v1 += x.y * y.y;
    }
    __shared__ float sm[256];
    sm[t] = v0 + v1; __syncthreads();
    for (int o = 128; o > 0; o >>= 1) { if (t < o) sm[t] += sm[t + o]; __syncthreads(); }
    float inv = mask / (sm[0] + 1e-30f);
    uint32_t H, L; splitbf(v0 * inv, v1 * inv, H, L);
    ctxH2[(size_t)bp*(LL/2) + t] = H;
    ctxL2[(size_t)bp*(LL/2) + t] = L;

    // ---- pair_att part ----
    __shared__ float smh[64], smt[64], invp[2];
    float ha = 0.f, ta = 0.f;
    if (t < 64) {
        if (t < MM) {
            float hm = emap[((size_t)b*EE + hi)*MM + t] * mask;
            float tm = emap[((size_t)b*EE + ti)*MM + t] * mask;
            ha = eatt[((size_t)b*EE + hi)*MM + t] * tm;
            ta = eatt[((size_t)b*EE + ti)*MM + t] * hm;
        }
        smh[t] = ha; smt[t] = ta;
    }
    __syncthreads();
    if (t < 32) {
        float sh = smh[t] + smh[t + 32];
        float st = smt[t] + smt[t + 32];
#pragma unroll
        for (int o = 16; o; o >>= 1) {
            sh += __shfl_xor_sync(0xffffffffu, sh, o);
            st += __shfl_xor_sync(0xffffffffu, st, o);
        }
        if (t == 0) { invp[0] = 1.f / (sh + 1e-30f); invp[1] = 1.f / (st + 1e-30f); }
    }
    __syncthreads();
    if (t < MM) {
        hattO[(size_t)bp*MM + t] = ha * invp[0];
        tattO[(size_t)bp*MM + t] = ta * invp[1];
    }
}

// ---------------- generic FFMA GEMM (em_tok only) ----------------
__global__ __launch_bounds__(256)
void gemm_k(const float* __restrict__ Ag, const float* __restrict__ Bg,
            float* __restrict__ Cg, int M, int N, int K,
            long long sA, long long sB, long long sC)
{
    const int BM = 64, BN = 64, BK = 16;
    int z = blockIdx.z;
    const float* A  = Ag + (long long)z * sA;
    const float* Bp = Bg + (long long)z * sB;
    float* C = Cg + (long long)z * sC;
    int row0 = blockIdx.y * BM;
    int col0 = blockIdx.x * BN;

    __shared__ float As[BK][BM + 1];
    __shared__ float Bs[BK][BN + 1];

    int tid = threadIdx.x;
    int tx = tid & 15, ty = tid >> 4;
    float acc[4][4] = {};

    for (int k0 = 0; k0 < K; k0 += BK) {
#pragma unroll
        for (int r = 0; r < 4; ++r) {
            int idx = tid + r * 256;
            int m = idx >> 4, k = idx & 15;
            float v = 0.f;
            if (row0 + m < M) v = A[(size_t)(row0 + m) * K + k0 + k];
            As[k][m] = v;
        }
#pragma unroll
        for (int r = 0; r < 4; ++r) {
            int idx = tid + r * 256;
            int k = idx >> 6, n = idx & 63;
            float v = 0.f;
            if (col0 + n < N) v = Bp[(size_t)(k0 + k) * N + col0 + n];
            Bs[k][n] = v;
        }
        __syncthreads();
#pragma unroll
        for (int k = 0; k < BK; ++k) {
            float a[4], bb[4];
#pragma unroll
            for (int i = 0; i < 4; ++i) a[i]  = As[k][ty * 4 + i];
#pragma unroll
            for (int j = 0; j < 4; ++j) bb[j] = Bs[k][tx * 4 + j];
#pragma unroll
            for (int i = 0; i < 4; ++i)
#pragma unroll
                for (int j = 0; j < 4; ++j) acc[i][j] += a[i] * bb[j];
        }
        __syncthreads();
    }

#pragma unroll
    for (int i = 0; i < 4; ++i) {
        int m = row0 + ty * 4 + i;
        if (m >= M) continue;
#pragma unroll
        for (int j = 0; j < 4; ++j) {
            int n = col0 + tx * 4 + j;
            if (n >= N) continue;
            C[(size_t)m * N + n] = acc[i][j];
        }
    }
}

// merged steps 2+3
__global__ __launch_bounds__(256)
void gemm23_k(const float* __restrict__ mmap, const float* __restrict__ context,
              const float* __restrict__ att_sum,
              float* __restrict__ mention, float* __restrict__ tmp1)
{
    const int BN = 64, BK = 16;
    int zz = blockIdx.z;
    int b = zz & 3, sel = zz >> 2;
    if (sel && blockIdx.x >= 8) return;
    int N = sel ? LL : DD;
    const float* A  = mmap + (size_t)b*MM*LL;
    const float* Bp = sel ? (att_sum + (size_t)b*LL*LL) : (context + (size_t)b*LL*DD);
    float* C = sel ? (tmp1 + (size_t)b*MM*LL) : (mention + (size_t)b*MM*DD);
    int col0 = blockIdx.x * BN;

    __shared__ float As[BK][65];
    __shared__ float Bs[BK][BN + 1];

    int tid = threadIdx.x;
    int tx = tid & 15, ty = tid >> 4;
    float acc[4][4] = {};

    for (int k0 = 0; k0 < LL; k0 += BK) {
#pragma unroll
        for (int r = 0; r < 4; ++r) {
            int idx = tid + r * 256;
            int m = idx >> 4, k = idx & 15;
            As[k][m] = (m < MM) ? A[(size_t)m * LL + k0 + k] : 0.f;
        }
#pragma unroll
        for (int r = 0; r < 4; ++r) {
            int idx = tid + r * 256;
            int k = idx >> 6, n = idx & 63;
            Bs[k][n] = Bp[(size_t)(k0 + k) * N + col0 + n];
        }
        __syncthreads();
#pragma unroll
        for (int k = 0; k < BK; ++k) {
            float a[4], bb[4];
#pragma unroll
            for (int i = 0; i < 4; ++i) a[i]  = As[k][ty * 4 + i];
#pragma unroll
            for (int j = 0; j < 4; ++j) bb[j] = Bs[k][tx * 4 + j];
#pragma unroll
            for (int i = 0; i < 4; ++i)
#pragma unroll
                for (int j = 0; j < 4; ++j) acc[i][j] += a[i] * bb[j];
        }
        __syncthreads();
    }

#pragma unroll
    for (int i = 0; i < 4; ++i) {
        int m = ty * 4 + i;
        if (m >= MM) continue;
#pragma unroll
        for (int j = 0; j < 4; ++j)
            C[(size_t)m * N + col0 + tx * 4 + j] = acc[i][j];
    }
}

// step 7: ent_att, BM=32 tile
__global__ __launch_bounds__(256)
void gemm32_k(const float* __restrict__ emtok, const float* __restrict__ att,
              float* __restrict__ entatt)
{
    int z = blockIdx.z;
    const float* A  = emtok + (size_t)(z / HH) * EE * LL;
    const float* Bp = att + (size_t)z * LL * LL;
    float* C = entatt + (size_t)z * EE * LL;
    int col0 = blockIdx.x * 64;

    __shared__ float As[16][34];
    __shared__ float Bs[16][68];

    int tid = threadIdx.x;
    int tx = tid & 15, ty = tid >> 4;
    float acc[2][4] = {};

    for (int k0 = 0; k0 < LL; k0 += 16) {
#pragma unroll
        for (int r = 0; r < 2; ++r) {
            int idx = tid + r * 256;
            int m = idx >> 4, k = idx & 15;
            As[k][m] = A[(size_t)m * LL + k0 + k];
        }
#pragma unroll
        for (int r = 0; r < 4; ++r) {
            int idx = tid + r * 256;
            int k = idx >> 6, n = idx & 63;
            Bs[k][n] = Bp[(size_t)(k0 + k) * LL + col0 + n];
        }
        __syncthreads();
#pragma unroll
        for (int k = 0; k < 16; ++k) {
            float2 a = *(const float2*)&As[k][ty * 2];
            float4 bv = *(const float4*)&Bs[k][tx * 4];
            acc[0][0] += a.x * bv.x; acc[0][1] += a.x * bv.y;
            acc[0][2] += a.x * bv.z; acc[0][3] += a.x * bv.w;
            acc[1][0] += a.y * bv.x; acc[1][1] += a.y * bv.y;
            acc[1][2] += a.y * bv.z; acc[1][3] += a.y * bv.w;
        }
        __syncthreads();
    }

#pragma unroll
    for (int i = 0; i < 2; ++i)
#pragma unroll
        for (int j = 0; j < 4; ++j)
            C[(size_t)(ty*2 + i) * LL + col0 + tx*4 + j] = acc[i][j];
}

// step 9 merged, fp16-split epilogue
__global__ __launch_bounds__(256)
void ht9_k(const float* __restrict__ tatt, const float* __restrict__ hatt,
           const float* __restrict__ mention,
           uint32_t* __restrict__ hH2, uint32_t* __restrict__ hL2,
           uint32_t* __restrict__ tH2, uint32_t* __restrict__ tL2)
{
    const int BM = 64, BN = 64, BK = 16;
    int zz = blockIdx.z;
    int b = zz & (BB - 1), sel = zz >> 2;
    const float* A  = (sel ? hatt : tatt) + (size_t)b * PP * MM;
    const float* Bp = mention + (size_t)b * MM * DD;
    uint32_t* CH = (sel ? tH2 : hH2) + (size_t)b * PP * (DD/2);
    uint32_t* CL = (sel ? tL2 : hL2) + (size_t)b * PP * (DD/2);
    int row0 = blockIdx.y * BM;
    int col0 = blockIdx.x * BN;

    __shared__ float As[BK][BM + 1];
    __shared__ float Bs[BK][BN + 1];

    int tid = threadIdx.x;
    int tx = tid & 15, ty = tid >> 4;
    float acc[4][4] = {};

    for (int k0 = 0; k0 < MM; k0 += BK) {
#pragma unroll
        for (int r = 0; r < 4; ++r) {
            int idx = tid + r * 256;
            int m = idx >> 4, k = idx & 15;
            As[k][m] = A[(size_t)(row0 + m) * MM + k0 + k];
        }
#pragma unroll
        for (int r = 0; r < 4; ++r) {
            int idx = tid + r * 256;
            int k = idx >> 6, n = idx & 63;
            Bs[k][n] = Bp[(size_t)(k0 + k) * DD + col0 + n];
        }
        __syncthreads();
#pragma unroll
        for (int k = 0; k < BK; ++k) {
            float a[4], bb[4];
#pragma unroll
            for (int i = 0; i < 4; ++i) a[i]  = As[k][ty * 4 + i];
#pragma unroll
            for (int j = 0; j < 4; ++j) bb[j] = Bs[k][tx * 4 + j];
#pragma unroll
            for (int i = 0; i < 4; ++i)
#pragma unroll
                for (int j = 0; j < 4; ++j) acc[i][j] += a[i] * bb[j];
        }
        __syncthreads();
    }

#pragma unroll
    for (int i = 0; i < 4; ++i) {
        int m = row0 + ty * 4 + i;
        int np = (col0 + tx * 4) >> 1;
        uint32_t H, L;
        splitfp16(acc[i][0], acc[i][1], H, L);
        CH[(size_t)m * (DD/2) + np]     = H;
        CL[(size_t)m * (DD/2) + np]     = L;
        splitfp16(acc[i][2], acc[i][3], H, L);
        CH[(size_t)m * (DD/2) + np + 1] = H;
        CL[(size_t)m * (DD/2) + np + 1] = L;
    }
}

// ---------------- bf16x3 NT GEMM: cinfo (fp16-split output) ----------------
#define BF_SMEM ((128*20 + 64*20) * 2 * 4)
__global__ __launch_bounds__(256)
void bf10_k(const uint32_t* __restrict__ AHg, const uint32_t* __restrict__ ALg,
            const uint32_t* __restrict__ BHg, const uint32_t* __restrict__ BLg,
            uint32_t* __restrict__ CH2g, uint32_t* __restrict__ CL2g)
{
    extern __shared__ uint32_t usm[];
    uint32_t* AsH = usm;
    uint32_t* AsL = AsH + 128*20;
    uint32_t* BsH = AsL + 128*20;
    uint32_t* BsL = BsH + 64*20;

    int z = blockIdx.z;
    const int KP = LL/2, N = DD;
    const uint32_t* AH = AHg + (size_t)z*PP*KP;
    const uint32_t* AL = ALg + (size_t)z*PP*KP;
    const uint32_t* BH = BHg + (size_t)z*DD*KP;
    const uint32_t* BL = BLg + (size_t)z*DD*KP;
    uint32_t* CH2 = CH2g + (size_t)z*PP*(DD/2);
    uint32_t* CL2 = CL2g + (size_t)z*PP*(DD/2);
    int row0 = blockIdx.y * 128, col0 = blockIdx.x * 64;
    int tid = threadIdx.x, lane = tid & 31, wid = tid >> 5;
    int m_off = (wid & 3) * 32, n_off = (wid >> 2) * 32;
    int g = lane >> 2, kq = lane & 3;

    float acc[2][4][4];
#pragma unroll
    for (int a = 0; a < 2; ++a)
#pragma unroll
        for (int b = 0; b < 4; ++b)
#pragma unroll
            for (int c = 0; c < 4; ++c) acc[a][b][c] = 0.f;

    for (int kp0 = 0; kp0 < KP; kp0 += 16) {
        __syncthreads();
#pragma unroll
        for (int r2 = 0; r2 < 2; ++r2) {
            int slot = tid + r2 * 256;
            int m = slot >> 2, q = slot & 3;
            *(uint4*)(AsH + m*20 + q*4) =
                *(const uint4*)(AH + (size_t)(row0 + m)*KP + kp0 + q*4);
            *(uint4*)(AsL + m*20 + q*4) =
                *(const uint4*)(AL + (size_t)(row0 + m)*KP + kp0 + q*4);
        }
        {
            int n = tid >> 2, q = tid & 3;
            *(uint4*)(BsH + n*20 + q*4) =
                *(const uint4*)(BH + (size_t)(col0 + n)*KP + kp0 + q*4);
            *(uint4*)(BsL + n*20 + q*4) =
                *(const uint4*)(BL + (size_t)(col0 + n)*KP + kp0 + q*4);
        }
        __syncthreads();
#pragma unroll
        for (int st = 0; st < 2; ++st) {
            int pb = st*8 + kq;
            uint32_t aH[2][4], aL[2][4];
#pragma unroll
            for (int mt = 0; mt < 2; ++mt) {
                int mr = m_off + mt*16 + g;
                aH[mt][0] = AsH[mr*20 + pb];       aL[mt][0] = AsL[mr*20 + pb];
                aH[mt][1] = AsH[(mr+8)*20 + pb];   aL[mt][1] = AsL[(mr+8)*20 + pb];
                aH[mt][2] = AsH[mr*20 + pb + 4];   aL[mt][2] = AsL[mr*20 + pb + 4];
                aH[mt][3] = AsH[(mr+8)*20 + pb+4]; aL[mt][3] = AsL[(mr+8)*20 + pb+4];
            }
#pragma unroll
            for (int nt = 0; nt < 4; ++nt) {
                int nr = n_off + nt*8 + g;
                uint32_t bH0 = BsH[nr*20 + pb], bH1 = BsH[nr*20 + pb + 4];
                uint32_t bL0 = BsL[nr*20 + pb], bL1 = BsL[nr*20 + pb + 4];
#pragma unroll
                for (int mt = 0; mt < 2; ++mt) {
                    mma_bf(acc[mt][nt], aH[mt], bH0, bH1);
                    mma_bf(acc[mt][nt], aH[mt], bL0, bL1);
                    mma_bf(acc[mt][nt], aL[mt], bH0, bH1);
                }
            }
        }
    }

#pragma unroll
    for (int mt = 0; mt < 2; ++mt) {
#pragma unroll
        for (int nt = 0; nt < 4; ++nt) {
            int mr = row0 + m_off + mt*16 + g;
            int nc = col0 + n_off + nt*8 + 2*kq;
            int np = nc >> 1;
            uint32_t H, L;
            splitfp16(acc[mt][nt][0], acc[mt][nt][1], H, L);
            CH2[(size_t)mr*(N/2) + np] = H; CL2[(size_t)mr*(N/2) + np] = L;
            splitfp16(acc[mt][nt][2], acc[mt][nt][3], H, L);
            CH2[(size_t)(mr+8)*(N/2) + np] = H; CL2[(size_t)(mr+8)*(N/2) + np] = L;
        }
    }
}

// ---------------- fp16 2-term fused tanh-linears ----------------
#define HF_SMEM ((128*20*2 + 64*20*2) * 4)
__global__ __launch_bounds__(256)
void hf1112_k(const uint32_t* __restrict__ hH2, const uint32_t* __restrict__ hL2,
              const uint32_t* __restrict__ tH2, const uint32_t* __restrict__ tL2,
              const uint32_t* __restrict__ hWf, const uint32_t* __restrict__ tWf,
              const uint32_t* __restrict__ cH2, const uint32_t* __restrict__ cL2,
              const uint32_t* __restrict__ hcWf, const uint32_t* __restrict__ tcWf,
              const float* __restrict__ hb, const float* __restrict__ tb,
              const float* __restrict__ hcb, const float* __restrict__ tcb,
              float* __restrict__ hf, float* __restrict__ tf)
{
    extern __shared__ uint32_t usm[];
    uint32_t* AsH = usm;
    uint32_t* AsL = AsH + 128*20;
    uint32_t* Bs  = AsL + 128*20;

    int zsel = blockIdx.z;
    const uint32_t* A1H = zsel ? tH2 : hH2;
    const uint32_t* A1L = zsel ? tL2 : hL2;
    const uint32_t* B1  = zsel ? tWf : hWf;
    const uint32_t* B2  = zsel ? tcWf : hcWf;
    const float* bias1 = zsel ? tb : hb;
    const float* bias2 = zsel ? tcb : hcb;
    float* C = zsel ? tf : hf;

    const int KP = DD/2, N = DD;
    int row0 = blockIdx.y * 128, col0 = blockIdx.x * 64;
    int tid = threadIdx.x, lane = tid & 31, wid = tid >> 5;
    int m_off = (wid & 3) * 32, n_off = (wid >> 2) * 32;
    int g = lane >> 2, kq = lane & 3;

    float acc[2][4][4];
#pragma unroll
    for (int a = 0; a < 2; ++a)
#pragma unroll
        for (int b = 0; b < 4; ++b)
#pragma unroll
            for (int c = 0; c < 4; ++c) acc[a][b][c] = 0.f;

    for (int pass = 0; pass < 2; ++pass) {
        const uint32_t* AH = pass ? cH2 : A1H;
        const uint32_t* AL = pass ? cL2 : A1L;
        const uint32_t* B  = pass ? B2  : B1;
        for (int kp0 = 0; kp0 < KP; kp0 += 16) {
            __syncthreads();
#pragma unroll
            for (int r2 = 0; r2 < 2; ++r2) {
                int slot = tid + r2 * 256;
                int m = slot >> 2, q = slot & 3;
                *(uint4*)(AsH + m*20 + q*4) =
                    *(const uint4*)(AH + (size_t)(row0 + m)*KP + kp0 + q*4);
                *(uint4*)(AsL + m*20 + q*4) =
                    *(const uint4*)(AL + (size_t)(row0 + m)*KP + kp0 + q*4);
            }
            {
                int n = tid >> 2, q = tid & 3;
                *(uint4*)(Bs + n*20 + q*4) =
                    *(const uint4*)(B + (size_t)(col0 + n)*KP + kp0 + q*4);
            }
            __syncthreads();
#pragma unroll
            for (int st = 0; st < 2; ++st) {
                int pb = st*8 + kq;
                uint32_t aH[2][4], aL[2][4];
#pragma unroll
                for (int mt = 0; mt < 2; ++mt) {
                    int mr = m_off + mt*16 + g;
                    aH[mt][0] = AsH[mr*20 + pb];       aL[mt][0] = AsL[mr*20 + pb];
                    aH[mt][1] = AsH[(mr+8)*20 + pb];   aL[mt][1] = AsL[(mr+8)*20 + pb];
                    aH[mt][2] = AsH[mr*20 + pb + 4];   aL[mt][2] = AsL[mr*20 + pb + 4];
                    aH[mt][3] = AsH[(mr+8)*20 + pb+4]; aL[mt][3] = AsL[(mr+8)*20 + pb+4];
                }
#pragma unroll
                for (int nt = 0; nt < 4; ++nt) {
                    int nr = n_off + nt*8 + g;
                    uint32_t b0 = Bs[nr*20 + pb], b1 = Bs[nr*20 + pb + 4];
#pragma unroll
                    for (int mt = 0; mt < 2; ++mt) {
                        mma_fp16(acc[mt][nt], aH[mt], b0, b1);
                        mma_fp16(acc[mt][nt], aL[mt], b0, b1);
                    }
                }
            }
        }
    }

#pragma unroll
    for (int mt = 0; mt < 2; ++mt) {
#pragma unroll
        for (int nt = 0; nt < 4; ++nt) {
            int mr = row0 + m_off + mt*16 + g;
            int nc = col0 + n_off + nt*8 + 2*kq;
            float b0 = bias1[nc]   + bias2[nc];
            float b1 = bias1[nc+1] + bias2[nc+1];
            C[(size_t)mr * N + nc]       = tanhf(acc[mt][nt][0] + b0);
            C[(size_t)mr * N + nc + 1]   = tanhf(acc[mt][nt][1] + b1);
            C[(size_t)(mr+8) * N + nc]   = tanhf(acc[mt][nt][2] + b0);
            C[(size_t)(mr+8) * N + nc+1] = tanhf(acc[mt][nt][3] + b1);
        }
    }
}

// ------- classifier: fp16 2-term, coop double-buffered smem W staging -------
#define CLAS_SMEM (128*17*4 + 2*128*33*4 + 2*4*WPAD*8)
__global__ __launch_bounds__(256, 1)
void clasmma_k(const float* __restrict__ Hf, const float* __restrict__ Tf,
               const uint2* __restrict__ Wt, float* __restrict__ part)
{
    extern __shared__ char smraw[];
    float*    hs  = (float*)smraw;
    uint32_t* tsH = (uint32_t*)(hs + 128*17);
    uint32_t* tsL = tsH + 128*33;
    uint2*    ws  = (uint2*)(tsL + 128*33);

    const int n = blockIdx.y, z = blockIdx.z;
    const int p0 = blockIdx.x * 128;
    int tid = threadIdx.x, lane = tid & 31, wid = tid >> 5;
    int pbase = (wid & 3) * 32, nbase = (wid >> 2) * 56;
    int g = lane >> 2, kq = lane & 3;

    for (int v = tid; v < 128*32; v += 256) {
        int p = v >> 5, q = v & 31;
        if (q < 16)
            hs[p*17 + q] = Hf[(size_t)(p0 + p)*DD + n*64 + z*16 + q];
        float t0 = Tf[(size_t)(p0 + p)*DD + n*64 + 2*q];
        float t1 = Tf[(size_t)(p0 + p)*DD + n*64 + 2*q + 1];
        uint32_t H, L; splitfp16(t0, t1, H, L);
        tsH[p*33 + q] = H; tsL[p*33 + q] = L;
    }
    {
        const uint2* Wg = Wt + (size_t)(n*64 + z*16) * WT_U2;
#pragma unroll
        for (int w = 0; w < 7; ++w) {
            int v = tid + w*256;
            int kq2 = v / 448, rem = v - kq2*448;
            ws[kq2*WPAD + rem] = Wg[v];
        }
    }
    __syncthreads();

    uint32_t tAH[2][4][4], tAL[2][4][4];
#pragma unroll
    for (int mt = 0; mt < 2; ++mt) {
        int pr = pbase + mt*16 + g;
#pragma unroll
        for (int s = 0; s < 4; ++s) {
            int pp = s*8 + kq;
            tAH[mt][s][0] = tsH[pr*33 + pp];       tAL[mt][s][0] = tsL[pr*33 + pp];
            tAH[mt][s][1] = tsH[(pr+8)*33 + pp];   tAL[mt][s][1] = tsL[(pr+8)*33 + pp];
            tAH[mt][s][2] = tsH[pr*33 + pp + 4];   tAL[mt][s][2] = tsL[pr*33 + pp + 4];
            tAH[mt][s][3] = tsH[(pr+8)*33 + pp+4]; tAL[mt][s][3] = tsL[(pr+8)*33 + pp+4];
        }
    }

    float acc[2][7][4];
#pragma unroll
    for (int a = 0; a < 2; ++a)
#pragma unroll
        for (int b = 0; b < 7; ++b)
#pragma unroll
            for (int c = 0; c < 4; ++c) acc[a][b][c] = 0.f;

    for (int ii = 0; ii < 16; ++ii) {
        uint2* wbuf  = ws + (ii & 1) * (4*WPAD);
        uint2* wnext = ws + ((ii + 1) & 1) * (4*WPAD);

        uint2 pf[7];
        if (ii < 15) {
            const uint2* Wg = Wt + (size_t)(n*64 + z*16 + ii + 1) * WT_U2;
#pragma unroll
            for (int w = 0; w < 7; ++w) pf[w] = Wg[tid + w*256];
        }

        float hv0[2], hv1[2];
#pragma unroll
        for (int mt = 0; mt < 2; ++mt) {
            int pr = pbase + mt*16 + g;
            hv0[mt] = hs[pr*17 + ii];
            hv1[mt] = hs[(pr+8)*17 + ii];
        }

        float tmp[2][7][4];
#pragma unroll
        for (int a = 0; a < 2; ++a)
#pragma unroll
            for (int b = 0; b < 7; ++b)
#pragma unroll
                for (int c = 0; c < 4; ++c) tmp[a][b][c] = 0.f;

#pragma unroll
        for (int s = 0; s < 4; ++s) {
#pragma unroll
            for (int nt = 0; nt < 7; ++nt) {
                int r = nbase + nt*8 + g;
                uint2 w2 = wbuf[kq*WPAD + s*112 + r];
#pragma unroll
                for (int mt = 0; mt < 2; ++mt) {
                    mma_fp16(tmp[mt][nt], tAH[mt][s], w2.x, w2.y);
                    mma_fp16(tmp[mt][nt], tAL[mt][s], w2.x, w2.y);
                }
            }
        }
#pragma unroll
        for (int mt = 0; mt < 2; ++mt)
#pragma unroll
            for (int nt = 0; nt < 7; ++nt) {
                acc[mt][nt][0] += hv0[mt] * tmp[mt][nt][0];
                acc[mt][nt][1] += hv0[mt] * tmp[mt][nt][1];
                acc[mt][nt][2] += hv1[mt] * tmp[mt][nt][2];
                acc[mt][nt][3] += hv1[mt] * tmp[mt][nt][3];
            }

        if (ii < 15) {
#pragma unroll
            for (int w = 0; w < 7; ++w) {
                int v = tid + w*256;
                int kq2 = v / 448, rem = v - kq2*448;
                wnext[kq2*WPAD + rem] = pf[w];
            }
        }
        __syncthreads();
    }

    int chunk = n*4 + z;
    float* po = part + (size_t)chunk * (BB*PP*RR);
#pragma unroll
    for (int mt = 0; mt < 2; ++mt) {
#pragma unroll
        for (int nt = 0; nt < 7; ++nt) {
            int p = p0 + pbase + mt*16 + g;
            int r = nbase + nt*8 + 2*kq;
            if (r < RR)   po[(size_t)p*RR + r]       = acc[mt][nt][0];
            if (r+1 < RR) po[(size_t)p*RR + r + 1]   = acc[mt][nt][1];
            if (r < RR)   po[(size_t)(p+8)*RR + r]   = acc[mt][nt][2];
            if (r+1 < RR) po[(size_t)(p+8)*RR + r+1] = acc[mt][nt][3];
        }
    }
}

__global__ void clas_red_k(const float* __restrict__ part,
                           const float* __restrict__ clasb,
                           float* __restrict__ out)
{
    int idx = blockIdx.x * 256 + threadIdx.x;
    if (idx >= BB * PP * RR) return;
    int r = idx % RR;
    float s = clasb[r];
#pragma unroll
    for (int c = 0; c < NCH; ++c) s += part[(size_t)c * (BB * PP * RR) + idx];
    out[idx] = s;
}

// ---------------- host ----------------
extern "C" void kernel_launch(void* const* d_in, const int* in_sizes, int n_in,
                              void* d_out, int out_size)
{
    const float* context   = (const float*)d_in[0];
    const float* attention = (const float*)d_in[1];
    const float* mmap      = (const float*)d_in[2];
    const float* emap      = (const float*)d_in[3];
    const int*   hts       = (const int*)d_in[4];
    const float* hW   = (const float*)d_in[5];
    const float* hb   = (const float*)d_in[6];
    const float* tW   = (const float*)d_in[7];
    const float* tb   = (const float*)d_in[8];
    const float* hcW  = (const float*)d_in[9];
    const float* hcb  = (const float*)d_in[10];
    const float* tcW  = (const float*)d_in[11];
    const float* tcb  = (const float*)d_in[12];
    const float* clasW = (const float*)d_in[13];
    const float* clasb = (const float*)d_in[14];
    float* out = (float*)d_out;

#define GETF(p, s) float* p; cudaGetSymbolAddress((void**)&p, s)
#define GETU(p, s) uint32_t* p; cudaGetSymbolAddress((void**)&p, s)
    GETF(att_sum, g_att_sum); GETF(mention, g_mention); GETF(tmp1, g_tmp1);
    GETF(eatt, g_eatt); GETF(emtok, g_emtok);
    GETF(entatt, g_entatt); GETF(hatt, g_hatt); GETF(tatt, g_tatt);
    GETU(ctxH2, g_ctxH2); GETU(ctxL2, g_ctxL2);
    GETU(hH2, g_hH2); GETU(hL2, g_hL2); GETU(tH2, g_tH2); GETU(tL2, g_tL2);
    GETU(cinfoH2, g_cinfoH2); GETU(cinfoL2, g_cinfoL2);
    GETF(hf, g_hf); GETF(tf, g_tf); GETF(part, g_part);
    GETU(hWf, g_hWf); GETU(tWf, g_tWf); GETU(hcWf, g_hcWf); GETU(tcWf, g_tcWf);
    GETU(ctxtH2, g_ctxtH2); GETU(ctxtL2, g_ctxtL2);
    uint2* Wt; cudaGetSymbolAddress((void**)&Wt, g_Wt);
#undef GETF
#undef GETU

    cudaFuncSetAttribute(clasmma_k, cudaFuncAttributeMaxDynamicSharedMemorySize, CLAS_SMEM);

    // 0+1) merged preprocessing + att_sum; coalesced clasW transform
    prep_k<<<8704, 256>>>(attention, att_sum, hW, tW, hcW, tcW,
                          hWf, tWf, hcWf, tcWf, context, ctxtH2, ctxtL2);
    wtrans2_k<<<NBK*64, 256>>>(clasW, Wt);

    // 2+3) mention & tmp1 merged
    gemm23_k<<<dim3(12,1,8),256>>>(mmap, context, att_sum, mention, tmp1);

    // 4+5) mention_att + entity_att fused
    matteatt_k<<<BB, 1024>>>(tmp1, mmap, emap, eatt);

    // 6) em_tok + normalize
    gemm_k<<<dim3(8,1,BB),256>>>(
        emap, mmap, emtok, EE, LL, MM,
        (long long)EE*MM, (long long)MM*LL, (long long)EE*LL);
    rownorm_k<<<BB*EE, 256>>>(emtok);

    // 7) ent_att (BM=32 tile)
    gemm32_k<<<dim3(8,1,BB*HH),256>>>(emtok, attention, entatt);

    // 8) ctx + pair_att merged
    ctxpair_k<<<BB*PP, 256>>>(hts, entatt, emap, eatt,
                              ctxH2, ctxL2, hatt, tatt);

    // 9) h, t merged (FFMA, fp16-split epilogue)
    ht9_k<<<dim3(12,8,2*BB),256>>>(tatt, hatt, mention, hH2, hL2, tH2, tL2);

    // 10) context_info (bf16x3 NT, fp16-split out)
    bf10_k<<<dim3(12,4,BB),256,BF_SMEM>>>(ctxH2, ctxL2, ctxtH2, ctxtL2,
                                          cinfoH2, cinfoL2);

    // 11+12) fused tanh-linears (fp16 2-term)
    hf1112_k<<<dim3(12,16,2),256,HF_SMEM>>>(
        hH2, hL2, tH2, tL2, hWf, tWf,
        cinfoH2, cinfoL2, hcWf, tcWf,
        hb, tb, hcb, tcb, hf, tf);

    // 13) classifier (fp16 2-term, smem-staged W)
    clasmma_k<<<dim3(BB*PP/128, NBK, 4), 256, CLAS_SMEM>>>(hf, tf, Wt, part);
    clas_red_k<<<(BB*PP*RR + 255)/256, 256>>>(part, clasb, out);
}

// round 14
// speedup vs baseline: 1.6395x; 1.6395x over previous
#include <cuda_runtime.h>
#include <cuda_bf16.h>
#include <cuda_fp16.h>
#include <cstdint>
#include <math.h>

#define BB 4
#define LL 512
#define DD 768
#define HH 12
#define MM 48
#define EE 32
#define PP 512
#define RR 97
#define NBK 12
#define NCH 48
#define KCLAS 49152
#define WT_U2 1792
#define WPAD 452
#define WPACK (DD*DD/2)

// ---------------- scratch ----------------
__device__ float g_att_sum[BB*LL*LL];
__device__ float g_mention[BB*MM*DD];
__device__ float g_tmp1[BB*MM*LL];
__device__ float g_matt[BB*MM*MM];
__device__ float g_eatt[BB*EE*MM];
__device__ float g_emtok[BB*EE*LL];
__device__ float g_entatt[BB*HH*EE*LL];
__device__ float g_hatt[BB*PP*MM];
__device__ float g_tatt[BB*PP*MM];
__device__ uint32_t g_ctxH2[BB*PP*LL/2];
__device__ uint32_t g_ctxL2[BB*PP*LL/2];
__device__ uint32_t g_hH2[BB*PP*DD/2];
__device__ uint32_t g_hL2[BB*PP*DD/2];
__device__ uint32_t g_tH2[BB*PP*DD/2];
__device__ uint32_t g_tL2[BB*PP*DD/2];
__device__ uint32_t g_cinfoH2[BB*PP*DD/2];
__device__ uint32_t g_cinfoL2[BB*PP*DD/2];
__device__ float g_hf[BB*PP*DD];
__device__ float g_tf[BB*PP*DD];
__device__ float g_part[NCH*BB*PP*RR];
__device__ uint32_t g_hWf[WPACK];
__device__ uint32_t g_tWf[WPACK];
__device__ uint32_t g_hcWf[WPACK];
__device__ uint32_t g_tcWf[WPACK];
__device__ uint32_t g_ctxtH2[BB*DD*LL/2];
__device__ uint32_t g_ctxtL2[BB*DD*LL/2];
__device__ uint2 g_Wt[NBK*64*WT_U2];

// ---------------- bf16 helpers ----------------
static __device__ __forceinline__ uint32_t pk2(float e0, float e1) {
    uint32_t r;
    asm("cvt.rn.bf16x2.f32 %0, %1, %2;" : "=r"(r) : "f"(e1), "f"(e0));
    return r;
}
static __device__ __forceinline__ void splitbf(float e0, float e1,
                                               uint32_t& H, uint32_t& L) {
    H = pk2(e0, e1);
    float h0 = __uint_as_float(H << 16);
    float h1 = __uint_as_float(H & 0xffff0000u);
    L = pk2(e0 - h0, e1 - h1);
}
static __device__ __forceinline__ void mma_bf(float* c, const uint32_t* a,
                                              uint32_t b0, uint32_t b1) {
    asm volatile(
        "mma.sync.aligned.m16n8k16.row.col.f32.bf16.bf16.f32 "
        "{%0,%1,%2,%3}, {%4,%5,%6,%7}, {%8,%9}, {%0,%1,%2,%3};"
        : "+f"(c[0]), "+f"(c[1]), "+f"(c[2]), "+f"(c[3])
        : "r"(a[0]), "r"(a[1]), "r"(a[2]), "r"(a[3]), "r"(b0), "r"(b1));
}

// ---------------- fp16 helpers ----------------
static __device__ __forceinline__ uint32_t pkh2(float e0, float e1) {
    __half2 h = __floats2half2_rn(e0, e1);
    return *(uint32_t*)&h;
}
static __device__ __forceinline__ void splitfp16(float e0, float e1,
                                                 uint32_t& H, uint32_t& L) {
    __half2 h = __floats2half2_rn(e0, e1);
    float2 hf = __half22float2(h);
    __half2 l = __floats2half2_rn(e0 - hf.x, e1 - hf.y);
    H = *(uint32_t*)&h;
    L = *(uint32_t*)&l;
}
static __device__ __forceinline__ void mma_fp16(float* c, const uint32_t* a,
                                                uint32_t b0, uint32_t b1) {
    asm volatile(
        "mma.sync.aligned.m16n8k16.row.col.f32.f16.f16.f32 "
        "{%0,%1,%2,%3}, {%4,%5,%6,%7}, {%8,%9}, {%0,%1,%2,%3};"
        : "+f"(c[0]), "+f"(c[1]), "+f"(c[2]), "+f"(c[3])
        : "r"(a[0]), "r"(a[1]), "r"(a[2]), "r"(a[3]), "r"(b0), "r"(b1));
}

// ---------------- merged preprocessing + att_sum ----------------
// regions: [0,1024) att_sum f4 | [1024,5632) weight fp16 pack |
//          [5632,8704) ctxt bf16 split | [8704,14080) clasW transform
__global__ void prep_k(const float* __restrict__ att, float* __restrict__ att_sum,
                       const float* __restrict__ hW, const float* __restrict__ tW,
                       const float* __restrict__ hcW, const float* __restrict__ tcW,
                       uint32_t* __restrict__ hWf, uint32_t* __restrict__ tWf,
                       uint32_t* __restrict__ hcWf, uint32_t* __restrict__ tcWf,
                       const float* __restrict__ context,
                       uint32_t* __restrict__ ctH, uint32_t* __restrict__ ctL,
                       const float* __restrict__ clasW, uint2* __restrict__ Wt)
{
    int blk = blockIdx.x, tid = threadIdx.x;
    if (blk < 1024) {
        int idx = blk * 256 + tid;
        int b  = idx >> 16;
        int lm = idx & (LL*LL/4 - 1);
        const float4* p = (const float4*)(att + (size_t)b*HH*LL*LL) + lm;
        float4 s = make_float4(0.f, 0.f, 0.f, 0.f);
#pragma unroll
        for (int h = 0; h < HH; ++h) {
            float4 v = p[(size_t)h*(LL*LL/4)];
            s.x += v.x; s.y += v.y; s.z += v.z; s.w += v.w;
        }
        ((float4*)att_sum)[idx] = s;
    } else if (blk < 5632) {
        int idx = (blk - 1024) * 256 + tid;
        int w = idx / WPACK, j = idx % WPACK;
        const float* src = (w == 0) ? hW : (w == 1) ? tW : (w == 2) ? hcW : tcW;
        uint32_t* dst = (w == 0) ? hWf : (w == 1) ? tWf : (w == 2) ? hcWf : tcWf;
        float2 v = ((const float2*)src)[j];
        dst[j] = pkh2(v.x, v.y);
    } else if (blk < 8704) {
        int idx = (blk - 5632) * 256 + tid;
        int lp = idx & 255;
        int bd = idx >> 8;
        int d = bd % DD, b = bd / DD;
        float e0 = context[((size_t)b*LL + 2*lp)     * DD + d];
        float e1 = context[((size_t)b*LL + 2*lp + 1) * DD + d];
        uint32_t h, l; splitbf(e0, e1, h, l);
        ctH[idx] = h; ctL[idx] = l;
    } else {
        int idx = (blk - 8704) * 256 + tid;
        int fi = idx % WT_U2;
        int ni = idx / WT_U2;
        int i = ni & 63, n = ni >> 6;
        int r  = fi % 112;
        int s  = (fi / 112) & 3;
        int kq = fi / 448;
        int j0 = s*16 + 2*kq;
        float w00 = 0.f, w01 = 0.f, w10 = 0.f, w11 = 0.f;
        if (r < RR) {
            const float* base = clasW + (size_t)r*KCLAS + (size_t)n*4096 + i*64;
            w00 = base[j0];     w01 = base[j0 + 1];
            w10 = base[j0 + 8]; w11 = base[j0 + 9];
        }
        uint2 o;
        o.x = pkh2(w00, w01);
        o.y = pkh2(w10, w11);
        Wt[idx] = o;
    }
}

// ---------------- small kernels ----------------
__global__ void rownorm_k(float* __restrict__ x)
{
    int row = blockIdx.x;
    float* p = x + (size_t)row * LL;
    int t = threadIdx.x;
    float v0 = p[t], v1 = p[t + 256];
    __shared__ float sm[256];
    sm[t] = v0 + v1; __syncthreads();
    for (int o = 128; o > 0; o >>= 1) { if (t < o) sm[t] += sm[t + o]; __syncthreads(); }
    float inv = 1.f / (sm[0] + 1e-30f);
    p[t] = v0 * inv; p[t + 256] = v1 * inv;
}

__global__ void pair_att_k(const int* __restrict__ hts,
                           const float* __restrict__ emap,
                           const float* __restrict__ eatt,
                           float* __restrict__ hattO, float* __restrict__ tattO)
{
    int bp = blockIdx.x;
    int b  = bp >> 9;
    int hi = hts[(size_t)bp*2], ti = hts[(size_t)bp*2 + 1];
    float mask = (hi + ti != 0) ? 1.f : 0.f;
    int t = threadIdx.x;
    float ha = 0.f, ta = 0.f;
    if (t < MM) {
        float hm = emap[((size_t)b*EE + hi)*MM + t] * mask;
        float tm = emap[((size_t)b*EE + ti)*MM + t] * mask;
        ha = eatt[((size_t)b*EE + hi)*MM + t] * tm;
        ta = eatt[((size_t)b*EE + ti)*MM + t] * hm;
    }
    __shared__ float smh[64], smt[64];
    smh[t] = ha; smt[t] = ta; __syncthreads();
    for (int o = 32; o > 0; o >>= 1) {
        if (t < o) { smh[t] += smh[t + o]; smt[t] += smt[t + o]; }
        __syncthreads();
    }
    float invh = 1.f / (smh[0] + 1e-30f);
    float invt = 1.f / (smt[0] + 1e-30f);
    if (t < MM) {
        hattO[(size_t)bp*MM + t] = ha * invh;
        tattO[(size_t)bp*MM + t] = ta * invt;
    }
}

__global__ void ctx_k(const int* __restrict__ hts,
                      const float* __restrict__ entatt,
                      uint32_t* __restrict__ ctxH2, uint32_t* __restrict__ ctxL2)
{
    int bp = blockIdx.x; int b = bp >> 9;
    int hi = hts[(size_t)bp*2], ti = hts[(size_t)bp*2 + 1];
    float mask = (hi + ti != 0) ? 1.f : 0.f;
    int t = threadIdx.x;
    const float* base = entatt + (size_t)b*HH*EE*LL;
    float v0 = 0.f, v1 = 0.f;
#pragma unroll
    for (int h = 0; h < HH; ++h) {
        const float2* ph = (const float2*)(base + ((size_t)h*EE + hi)*LL);
        const float2* pt = (const float2*)(base + ((size_t)h*EE + ti)*LL);
        float2 x = ph[t], y = pt[t];
        v0 += x.x * y.x;
        v1 += x.y * y.y;
    }
    __shared__ float sm[256];
    sm[t] = v0 + v1; __syncthreads();
    for (int o = 128; o > 0; o >>= 1) { if (t < o) sm[t] += sm[t + o]; __syncthreads(); }
    float inv = mask / (sm[0] + 1e-30f);
    uint32_t H, L; splitbf(v0 * inv, v1 * inv, H, L);
    ctxH2[(size_t)bp*(LL/2) + t] = H;
    ctxL2[(size_t)bp*(LL/2) + t] = L;
}

__global__ void matt_k(const float* __restrict__ tmp1, const float* __restrict__ mmap,
                       float* __restrict__ matt)
{
    int gw = (blockIdx.x * 256 + threadIdx.x) >> 5;
    if (gw >= BB*MM*MM) return;
    int lane = threadIdx.x & 31;
    int b = gw / (MM*MM);
    int rem = gw % (MM*MM);
    int m = rem / MM, j = rem % MM;
    const float4* a = (const float4*)(tmp1 + ((size_t)b*MM + m)*LL);
    const float4* c = (const float4*)(mmap + ((size_t)b*MM + j)*LL);
    float s = 0.f;
#pragma unroll
    for (int k = lane; k < 128; k += 32) {
        float4 x = a[k], y = c[k];
        s += x.x*y.x + x.y*y.y + x.z*y.z + x.w*y.w;
    }
#pragma unroll
    for (int o = 16; o; o >>= 1) s += __shfl_xor_sync(0xffffffffu, s, o);
    if (lane == 0) matt[gw] = s;
}

// eatt: warp per output (b,e,j), lane-parallel over m=48
__global__ void eatt_k(const float* __restrict__ emap, const float* __restrict__ matt,
                       float* __restrict__ eatt)
{
    int gw = (blockIdx.x * 256 + threadIdx.x) >> 5;
    if (gw >= BB*EE*MM) return;
    int lane = threadIdx.x & 31;
    int b = gw / (EE*MM);
    int rem = gw % (EE*MM);
    int e = rem / MM, j = rem % MM;
    const float* em = emap + ((size_t)b*EE + e)*MM;
    const float* mt = matt + (size_t)b*MM*MM + j;
    float s = em[lane] * mt[lane*MM];
    if (lane < 16) s += em[lane + 32] * mt[(lane + 32)*MM];
#pragma unroll
    for (int o = 16; o; o >>= 1) s += __shfl_xor_sync(0xffffffffu, s, o);
    if (lane == 0) eatt[gw] = s;
}

// ---------------- generic FFMA GEMM (em_tok only) ----------------
__global__ __launch_bounds__(256)
void gemm_k(const float* __restrict__ Ag, const float* __restrict__ Bg,
            float* __restrict__ Cg, int M, int N, int K,
            long long sA, long long sB, long long sC)
{
    const int BM = 64, BN = 64, BK = 16;
    int z = blockIdx.z;
    const float* A  = Ag + (long long)z * sA;
    const float* Bp = Bg + (long long)z * sB;
    float* C = Cg + (long long)z * sC;
    int row0 = blockIdx.y * BM;
    int col0 = blockIdx.x * BN;

    __shared__ float As[BK][BM + 1];
    __shared__ float Bs[BK][BN + 1];

    int tid = threadIdx.x;
    int tx = tid & 15, ty = tid >> 4;
    float acc[4][4] = {};

    for (int k0 = 0; k0 < K; k0 += BK) {
#pragma unroll
        for (int r = 0; r < 4; ++r) {
            int idx = tid + r * 256;
            int m = idx >> 4, k = idx & 15;
            float v = 0.f;
            if (row0 + m < M) v = A[(size_t)(row0 + m) * K + k0 + k];
            As[k][m] = v;
        }
#pragma unroll
        for (int r = 0; r < 4; ++r) {
            int idx = tid + r * 256;
            int k = idx >> 6, n = idx & 63;
            float v = 0.f;
            if (col0 + n < N) v = Bp[(size_t)(k0 + k) * N + col0 + n];
            Bs[k][n] = v;
        }
        __syncthreads();
#pragma unroll
        for (int k = 0; k < BK; ++k) {
            float a[4], bb[4];
#pragma unroll
            for (int i = 0; i < 4; ++i) a[i]  = As[k][ty * 4 + i];
#pragma unroll
            for (int j = 0; j < 4; ++j) bb[j] = Bs[k][tx * 4 + j];
#pragma unroll
            for (int i = 0; i < 4; ++i)
#pragma unroll
                for (int j = 0; j < 4; ++j) acc[i][j] += a[i] * bb[j];
        }
        __syncthreads();
    }

#pragma unroll
    for (int i = 0; i < 4; ++i) {
        int m = row0 + ty * 4 + i;
        if (m >= M) continue;
#pragma unroll
        for (int j = 0; j < 4; ++j) {
            int n = col0 + tx * 4 + j;
            if (n >= N) continue;
            C[(size_t)m * N + n] = acc[i][j];
        }
    }
}

// merged steps 2+3
__global__ __launch_bounds__(256)
void gemm23_k(const float* __restrict__ mmap, const float* __restrict__ context,
              const float* __restrict__ att_sum,
              float* __restrict__ mention, float* __restrict__ tmp1)
{
    const int BN = 64, BK = 16;
    int zz = blockIdx.z;
    int b = zz & 3, sel = zz >> 2;
    if (sel && blockIdx.x >= 8) return;
    int N = sel ? LL : DD;
    const float* A  = mmap + (size_t)b*MM*LL;
    const float* Bp = sel ? (att_sum + (size_t)b*LL*LL) : (context + (size_t)b*LL*DD);
    float* C = sel ? (tmp1 + (size_t)b*MM*LL) : (mention + (size_t)b*MM*DD);
    int col0 = blockIdx.x * BN;

    __shared__ float As[BK][65];
    __shared__ float Bs[BK][BN + 1];

    int tid = threadIdx.x;
    int tx = tid & 15, ty = tid >> 4;
    float acc[4][4] = {};

    for (int k0 = 0; k0 < LL; k0 += BK) {
#pragma unroll
        for (int r = 0; r < 4; ++r) {
            int idx = tid + r * 256;
            int m = idx >> 4, k = idx & 15;
            As[k][m] = (m < MM) ? A[(size_t)m * LL + k0 + k] : 0.f;
        }
#pragma unroll
        for (int r = 0; r < 4; ++r) {
            int idx = tid + r * 256;
            int k = idx >> 6, n = idx & 63;
            Bs[k][n] = Bp[(size_t)(k0 + k) * N + col0 + n];
        }
        __syncthreads();
#pragma unroll
        for (int k = 0; k < BK; ++k) {
            float a[4], bb[4];
#pragma unroll
            for (int i = 0; i < 4; ++i) a[i]  = As[k][ty * 4 + i];
#pragma unroll
            for (int j = 0; j < 4; ++j) bb[j] = Bs[k][tx * 4 + j];
#pragma unroll
            for (int i = 0; i < 4; ++i)
#pragma unroll
                for (int j = 0; j < 4; ++j) acc[i][j] += a[i] * bb[j];
        }
        __syncthreads();
    }

#pragma unroll
    for (int i = 0; i < 4; ++i) {
        int m = ty * 4 + i;
        if (m >= MM) continue;
#pragma unroll
        for (int j = 0; j < 4; ++j)
            C[(size_t)m * N + col0 + tx * 4 + j] = acc[i][j];
    }
}

// step 7: ent_att, BM=32 tile
__global__ __launch_bounds__(256)
void gemm32_k(const float* __restrict__ emtok, const float* __restrict__ att,
              float* __restrict__ entatt)
{
    int z = blockIdx.z;
    const float* A  = emtok + (size_t)(z / HH) * EE * LL;
    const float* Bp = att + (size_t)z * LL * LL;
    float* C = entatt + (size_t)z * EE * LL;
    int col0 = blockIdx.x * 64;

    __shared__ float As[16][34];
    __shared__ float Bs[16][68];

    int tid = threadIdx.x;
    int tx = tid & 15, ty = tid >> 4;
    float acc[2][4] = {};

    for (int k0 = 0; k0 < LL; k0 += 16) {
#pragma unroll
        for (int r = 0; r < 2; ++r) {
            int idx = tid + r * 256;
            int m = idx >> 4, k = idx & 15;
            As[k][m] = A[(size_t)m * LL + k0 + k];
        }
#pragma unroll
        for (int r = 0; r < 4; ++r) {
            int idx = tid + r * 256;
            int k = idx >> 6, n = idx & 63;
            Bs[k][n] = Bp[(size_t)(k0 + k) * LL + col0 + n];
        }
        __syncthreads();
#pragma unroll
        for (int k = 0; k < 16; ++k) {
            float2 a = *(const float2*)&As[k][ty * 2];
            float4 bv = *(const float4*)&Bs[k][tx * 4];
            acc[0][0] += a.x * bv.x; acc[0][1] += a.x * bv.y;
            acc[0][2] += a.x * bv.z; acc[0][3] += a.x * bv.w;
            acc[1][0] += a.y * bv.x; acc[1][1] += a.y * bv.y;
            acc[1][2] += a.y * bv.z; acc[1][3] += a.y * bv.w;
        }
        __syncthreads();
    }

#pragma unroll
    for (int i = 0; i < 2; ++i)
#pragma unroll
        for (int j = 0; j < 4; ++j)
            C[(size_t)(ty*2 + i) * LL + col0 + tx*4 + j] = acc[i][j];
}

// step 9 merged, fp16-split epilogue
__global__ __launch_bounds__(256)
void ht9_k(const float* __restrict__ tatt, const float* __restrict__ hatt,
           const float* __restrict__ mention,
           uint32_t* __restrict__ hH2, uint32_t* __restrict__ hL2,
           uint32_t* __restrict__ tH2, uint32_t* __restrict__ tL2)
{
    const int BM = 64, BN = 64, BK = 16;
    int zz = blockIdx.z;
    int b = zz & (BB - 1), sel = zz >> 2;
    const float* A  = (sel ? hatt : tatt) + (size_t)b * PP * MM;
    const float* Bp = mention + (size_t)b * MM * DD;
    uint32_t* CH = (sel ? tH2 : hH2) + (size_t)b * PP * (DD/2);
    uint32_t* CL = (sel ? tL2 : hL2) + (size_t)b * PP * (DD/2);
    int row0 = blockIdx.y * BM;
    int col0 = blockIdx.x * BN;

    __shared__ float As[BK][BM + 1];
    __shared__ float Bs[BK][BN + 1];

    int tid = threadIdx.x;
    int tx = tid & 15, ty = tid >> 4;
    float acc[4][4] = {};

    for (int k0 = 0; k0 < MM; k0 += BK) {
#pragma unroll
        for (int r = 0; r < 4; ++r) {
            int idx = tid + r * 256;
            int m = idx >> 4, k = idx & 15;
            As[k][m] = A[(size_t)(row0 + m) * MM + k0 + k];
        }
#pragma unroll
        for (int r = 0; r < 4; ++r) {
            int idx = tid + r * 256;
            int k = idx >> 6, n = idx & 63;
            Bs[k][n] = Bp[(size_t)(k0 + k) * DD + col0 + n];
        }
        __syncthreads();
#pragma unroll
        for (int k = 0; k < BK; ++k) {
            float a[4], bb[4];
#pragma unroll
            for (int i = 0; i < 4; ++i) a[i]  = As[k][ty * 4 + i];
#pragma unroll
            for (int j = 0; j < 4; ++j) bb[j] = Bs[k][tx * 4 + j];
#pragma unroll
            for (int i = 0; i < 4; ++i)
#pragma unroll
                for (int j = 0; j < 4; ++j) acc[i][j] += a[i] * bb[j];
        }
        __syncthreads();
    }

#pragma unroll
    for (int i = 0; i < 4; ++i) {
        int m = row0 + ty * 4 + i;
        int np = (col0 + tx * 4) >> 1;
        uint32_t H, L;
        splitfp16(acc[i][0], acc[i][1], H, L);
        CH[(size_t)m * (DD/2) + np]     = H;
        CL[(size_t)m * (DD/2) + np]     = L;
        splitfp16(acc[i][2], acc[i][3], H, L);
        CH[(size_t)m * (DD/2) + np + 1] = H;
        CL[(size_t)m * (DD/2) + np + 1] = L;
    }
}

// ---------------- bf16x3 NT GEMM: cinfo (fp16-split output) ----------------
#define BF_SMEM ((128*20 + 64*20) * 2 * 4)
__global__ __launch_bounds__(256)
void bf10_k(const uint32_t* __restrict__ AHg, const uint32_t* __restrict__ ALg,
            const uint32_t* __restrict__ BHg, const uint32_t* __restrict__ BLg,
            uint32_t* __restrict__ CH2g, uint32_t* __restrict__ CL2g)
{
    extern __shared__ uint32_t usm[];
    uint32_t* AsH = usm;
    uint32_t* AsL = AsH + 128*20;
    uint32_t* BsH = AsL + 128*20;
    uint32_t* BsL = BsH + 64*20;

    int z = blockIdx.z;
    const int KP = LL/2, N = DD;
    const uint32_t* AH = AHg + (size_t)z*PP*KP;
    const uint32_t* AL = ALg + (size_t)z*PP*KP;
    const uint32_t* BH = BHg + (size_t)z*DD*KP;
    const uint32_t* BL = BLg + (size_t)z*DD*KP;
    uint32_t* CH2 = CH2g + (size_t)z*PP*(DD/2);
    uint32_t* CL2 = CL2g + (size_t)z*PP*(DD/2);
    int row0 = blockIdx.y * 128, col0 = blockIdx.x * 64;
    int tid = threadIdx.x, lane = tid & 31, wid = tid >> 5;
    int m_off = (wid & 3) * 32, n_off = (wid >> 2) * 32;
    int g = lane >> 2, kq = lane & 3;

    float acc[2][4][4];
#pragma unroll
    for (int a = 0; a < 2; ++a)
#pragma unroll
        for (int b = 0; b < 4; ++b)
#pragma unroll
            for (int c = 0; c < 4; ++c) acc[a][b][c] = 0.f;

    for (int kp0 = 0; kp0 < KP; kp0 += 16) {
        __syncthreads();
#pragma unroll
        for (int r2 = 0; r2 < 2; ++r2) {
            int slot = tid + r2 * 256;
            int m = slot >> 2, q = slot & 3;
            *(uint4*)(AsH + m*20 + q*4) =
                *(const uint4*)(AH + (size_t)(row0 + m)*KP + kp0 + q*4);
            *(uint4*)(AsL + m*20 + q*4) =
                *(const uint4*)(AL + (size_t)(row0 + m)*KP + kp0 + q*4);
        }
        {
            int n = tid >> 2, q = tid & 3;
            *(uint4*)(BsH + n*20 + q*4) =
                *(const uint4*)(BH + (size_t)(col0 + n)*KP + kp0 + q*4);
            *(uint4*)(BsL + n*20 + q*4) =
                *(const uint4*)(BL + (size_t)(col0 + n)*KP + kp0 + q*4);
        }
        __syncthreads();
#pragma unroll
        for (int st = 0; st < 2; ++st) {
            int pb = st*8 + kq;
            uint32_t aH[2][4], aL[2][4];
#pragma unroll
            for (int mt = 0; mt < 2; ++mt) {
                int mr = m_off + mt*16 + g;
                aH[mt][0] = AsH[mr*20 + pb];       aL[mt][0] = AsL[mr*20 + pb];
                aH[mt][1] = AsH[(mr+8)*20 + pb];   aL[mt][1] = AsL[(mr+8)*20 + pb];
                aH[mt][2] = AsH[mr*20 + pb + 4];   aL[mt][2] = AsL[mr*20 + pb + 4];
                aH[mt][3] = AsH[(mr+8)*20 + pb+4]; aL[mt][3] = AsL[(mr+8)*20 + pb+4];
            }
#pragma unroll
            for (int nt = 0; nt < 4; ++nt) {
                int nr = n_off + nt*8 + g;
                uint32_t bH0 = BsH[nr*20 + pb], bH1 = BsH[nr*20 + pb + 4];
                uint32_t bL0 = BsL[nr*20 + pb], bL1 = BsL[nr*20 + pb + 4];
#pragma unroll
                for (int mt = 0; mt < 2; ++mt) {
                    mma_bf(acc[mt][nt], aH[mt], bH0, bH1);
                    mma_bf(acc[mt][nt], aH[mt], bL0, bL1);
                    mma_bf(acc[mt][nt], aL[mt], bH0, bH1);
                }
            }
        }
    }

#pragma unroll
    for (int mt = 0; mt < 2; ++mt) {
#pragma unroll
        for (int nt = 0; nt < 4; ++nt) {
            int mr = row0 + m_off + mt*16 + g;
            int nc = col0 + n_off + nt*8 + 2*kq;
            int np = nc >> 1;
            uint32_t H, L;
            splitfp16(acc[mt][nt][0], acc[mt][nt][1], H, L);
            CH2[(size_t)mr*(N/2) + np] = H; CL2[(size_t)mr*(N/2) + np] = L;
            splitfp16(acc[mt][nt][2], acc[mt][nt][3], H, L);
            CH2[(size_t)(mr+8)*(N/2) + np] = H; CL2[(size_t)(mr+8)*(N/2) + np] = L;
        }
    }
}

// ---------------- fp16 2-term fused tanh-linears ----------------
#define HF_SMEM ((128*20*2 + 64*20*2) * 4)
__global__ __launch_bounds__(256)
void hf1112_k(const uint32_t* __restrict__ hH2, const uint32_t* __restrict__ hL2,
              const uint32_t* __restrict__ tH2, const uint32_t* __restrict__ tL2,
              const uint32_t* __restrict__ hWf, const uint32_t* __restrict__ tWf,
              const uint32_t* __restrict__ cH2, const uint32_t* __restrict__ cL2,
              const uint32_t* __restrict__ hcWf, const uint32_t* __restrict__ tcWf,
              const float* __restrict__ hb, const float* __restrict__ tb,
              const float* __restrict__ hcb, const float* __restrict__ tcb,
              float* __restrict__ hf, float* __restrict__ tf)
{
    extern __shared__ uint32_t usm[];
    uint32_t* AsH = usm;
    uint32_t* AsL = AsH + 128*20;
    uint32_t* Bs  = AsL + 128*20;

    int zsel = blockIdx.z;
    const uint32_t* A1H = zsel ? tH2 : hH2;
    const uint32_t* A1L = zsel ? tL2 : hL2;
    const uint32_t* B1  = zsel ? tWf : hWf;
    const uint32_t* B2  = zsel ? tcWf : hcWf;
    const float* bias1 = zsel ? tb : hb;
    const float* bias2 = zsel ? tcb : hcb;
    float* C = zsel ? tf : hf;

    const int KP = DD/2, N = DD;
    int row0 = blockIdx.y * 128, col0 = blockIdx.x * 64;
    int tid = threadIdx.x, lane = tid & 31, wid = tid >> 5;
    int m_off = (wid & 3) * 32, n_off = (wid >> 2) * 32;
    int g = lane >> 2, kq = lane & 3;

    float acc[2][4][4];
#pragma unroll
    for (int a = 0; a < 2; ++a)
#pragma unroll
        for (int b = 0; b < 4; ++b)
#pragma unroll
            for (int c = 0; c < 4; ++c) acc[a][b][c] = 0.f;

    for (int pass = 0; pass < 2; ++pass) {
        const uint32_t* AH = pass ? cH2 : A1H;
        const uint32_t* AL = pass ? cL2 : A1L;
        const uint32_t* B  = pass ? B2  : B1;
        for (int kp0 = 0; kp0 < KP; kp0 += 16) {
            __syncthreads();
#pragma unroll
            for (int r2 = 0; r2 < 2; ++r2) {
                int slot = tid + r2 * 256;
                int m = slot >> 2, q = slot & 3;
                *(uint4*)(AsH + m*20 + q*4) =
                    *(const uint4*)(AH + (size_t)(row0 + m)*KP + kp0 + q*4);
                *(uint4*)(AsL + m*20 + q*4) =
                    *(const uint4*)(AL + (size_t)(row0 + m)*KP + kp0 + q*4);
            }
            {
                int n = tid >> 2, q = tid & 3;
                *(uint4*)(Bs + n*20 + q*4) =
                    *(const uint4*)(B + (size_t)(col0 + n)*KP + kp0 + q*4);
            }
            __syncthreads();
#pragma unroll
            for (int st = 0; st < 2; ++st) {
                int pb = st*8 + kq;
                uint32_t aH[2][4], aL[2][4];
#pragma unroll
                for (int mt = 0; mt < 2; ++mt) {
                    int mr = m_off + mt*16 + g;
                    aH[mt][0] = AsH[mr*20 + pb];       aL[mt][0] = AsL[mr*20 + pb];
                    aH[mt][1] = AsH[(mr+8)*20 + pb];   aL[mt][1] = AsL[(mr+8)*20 + pb];
                    aH[mt][2] = AsH[mr*20 + pb + 4];   aL[mt][2] = AsL[mr*20 + pb + 4];
                    aH[mt][3] = AsH[(mr+8)*20 + pb+4]; aL[mt][3] = AsL[(mr+8)*20 + pb+4];
                }
#pragma unroll
                for (int nt = 0; nt < 4; ++nt) {
                    int nr = n_off + nt*8 + g;
                    uint32_t b0 = Bs[nr*20 + pb], b1 = Bs[nr*20 + pb + 4];
#pragma unroll
                    for (int mt = 0; mt < 2; ++mt) {
                        mma_fp16(acc[mt][nt], aH[mt], b0, b1);
                        mma_fp16(acc[mt][nt], aL[mt], b0, b1);
                    }
                }
            }
        }
    }

#pragma unroll
    for (int mt = 0; mt < 2; ++mt) {
#pragma unroll
        for (int nt = 0; nt < 4; ++nt) {
            int mr = row0 + m_off + mt*16 + g;
            int nc = col0 + n_off + nt*8 + 2*kq;
            float b0 = bias1[nc]   + bias2[nc];
            float b1 = bias1[nc+1] + bias2[nc+1];
            C[(size_t)mr * N + nc]       = tanhf(acc[mt][nt][0] + b0);
            C[(size_t)mr * N + nc + 1]   = tanhf(acc[mt][nt][1] + b1);
            C[(size_t)(mr+8) * N + nc]   = tanhf(acc[mt][nt][2] + b0);
            C[(size_t)(mr+8) * N + nc+1] = tanhf(acc[mt][nt][3] + b1);
        }
    }
}

// ------- classifier: fp16 2-term, coop double-buffered smem W staging -------
#define CLAS_SMEM (128*17*4 + 2*128*33*4 + 2*4*WPAD*8)
__global__ __launch_bounds__(256, 1)
void clasmma_k(const float* __restrict__ Hf, const float* __restrict__ Tf,
               const uint2* __restrict__ Wt, float* __restrict__ part)
{
    extern __shared__ char smraw[];
    float*    hs  = (float*)smraw;
    uint32_t* tsH = (uint32_t*)(hs + 128*17);
    uint32_t* tsL = tsH + 128*33;
    uint2*    ws  = (uint2*)(tsL + 128*33);

    const int n = blockIdx.y, z = blockIdx.z;
    const int p0 = blockIdx.x * 128;
    int tid = threadIdx.x, lane = tid & 31, wid = tid >> 5;
    int pbase = (wid & 3) * 32, nbase = (wid >> 2) * 56;
    int g = lane >> 2, kq = lane & 3;

    for (int v = tid; v < 128*32; v += 256) {
        int p = v >> 5, q = v & 31;
        if (q < 16)
            hs[p*17 + q] = Hf[(size_t)(p0 + p)*DD + n*64 + z*16 + q];
        float t0 = Tf[(size_t)(p0 + p)*DD + n*64 + 2*q];
        float t1 = Tf[(size_t)(p0 + p)*DD + n*64 + 2*q + 1];
        uint32_t H, L; splitfp16(t0, t1, H, L);
        tsH[p*33 + q] = H; tsL[p*33 + q] = L;
    }
    {
        const uint2* Wg = Wt + (size_t)(n*64 + z*16) * WT_U2;
#pragma unroll
        for (int w = 0; w < 7; ++w) {
            int v = tid + w*256;
            int kq2 = v / 448, rem = v - kq2*448;
            ws[kq2*WPAD + rem] = Wg[v];
        }
    }
    __syncthreads();

    uint32_t tAH[2][4][4], tAL[2][4][4];
#pragma unroll
    for (int mt = 0; mt < 2; ++mt) {
        int pr = pbase + mt*16 + g;
#pragma unroll
        for (int s = 0; s < 4; ++s) {
            int pp = s*8 + kq;
            tAH[mt][s][0] = tsH[pr*33 + pp];       tAL[mt][s][0] = tsL[pr*33 + pp];
            tAH[mt][s][1] = tsH[(pr+8)*33 + pp];   tAL[mt][s][1] = tsL[(pr+8)*33 + pp];
            tAH[mt][s][2] = tsH[pr*33 + pp + 4];   tAL[mt][s][2] = tsL[pr*33 + pp + 4];
            tAH[mt][s][3] = tsH[(pr+8)*33 + pp+4]; tAL[mt][s][3] = tsL[(pr+8)*33 + pp+4];
        }
    }

    float acc[2][7][4];
#pragma unroll
    for (int a = 0; a < 2; ++a)
#pragma unroll
        for (int b = 0; b < 7; ++b)
#pragma unroll
            for (int c = 0; c < 4; ++c) acc[a][b][c] = 0.f;

    for (int ii = 0; ii < 16; ++ii) {
        uint2* wbuf  = ws + (ii & 1) * (4*WPAD);
        uint2* wnext = ws + ((ii + 1) & 1) * (4*WPAD);

        uint2 pf[7];
        if (ii < 15) {
            const uint2* Wg = Wt + (size_t)(n*64 + z*16 + ii + 1) * WT_U2;
#pragma unroll
            for (int w = 0; w < 7; ++w) pf[w] = Wg[tid + w*256];
        }

        float hv0[2], hv1[2];
#pragma unroll
        for (int mt = 0; mt < 2; ++mt) {
            int pr = pbase + mt*16 + g;
            hv0[mt] = hs[pr*17 + ii];
            hv1[mt] = hs[(pr+8)*17 + ii];
        }

        float tmp[2][7][4];
#pragma unroll
        for (int a = 0; a < 2; ++a)
#pragma unroll
            for (int b = 0; b < 7; ++b)
#pragma unroll
                for (int c = 0; c < 4; ++c) tmp[a][b][c] = 0.f;

#pragma unroll
        for (int s = 0; s < 4; ++s) {
#pragma unroll
            for (int nt = 0; nt < 7; ++nt) {
                int r = nbase + nt*8 + g;
                uint2 w2 = wbuf[kq*WPAD + s*112 + r];
#pragma unroll
                for (int mt = 0; mt < 2; ++mt) {
                    mma_fp16(tmp[mt][nt], tAH[mt][s], w2.x, w2.y);
                    mma_fp16(tmp[mt][nt], tAL[mt][s], w2.x, w2.y);
                }
            }
        }
#pragma unroll
        for (int mt = 0; mt < 2; ++mt)
#pragma unroll
            for (int nt = 0; nt < 7; ++nt) {
                acc[mt][nt][0] += hv0[mt] * tmp[mt][nt][0];
                acc[mt][nt][1] += hv0[mt] * tmp[mt][nt][1];
                acc[mt][nt][2] += hv1[mt] * tmp[mt][nt][2];
                acc[mt][nt][3] += hv1[mt] * tmp[mt][nt][3];
            }

        if (ii < 15) {
#pragma unroll
            for (int w = 0; w < 7; ++w) {
                int v = tid + w*256;
                int kq2 = v / 448, rem = v - kq2*448;
                wnext[kq2*WPAD + rem] = pf[w];
            }
        }
        __syncthreads();
    }

    int chunk = n*4 + z;
    float* po = part + (size_t)chunk * (BB*PP*RR);
#pragma unroll
    for (int mt = 0; mt < 2; ++mt) {
#pragma unroll
        for (int nt = 0; nt < 7; ++nt) {
            int p = p0 + pbase + mt*16 + g;
            int r = nbase + nt*8 + 2*kq;
            if (r < RR)   po[(size_t)p*RR + r]       = acc[mt][nt][0];
            if (r+1 < RR) po[(size_t)p*RR + r + 1]   = acc[mt][nt][1];
            if (r < RR)   po[(size_t)(p+8)*RR + r]   = acc[mt][nt][2];
            if (r+1 < RR) po[(size_t)(p+8)*RR + r+1] = acc[mt][nt][3];
        }
    }
}

__global__ void clas_red_k(const float* __restrict__ part,
                           const float* __restrict__ clasb,
                           float* __restrict__ out)
{
    int idx = blockIdx.x * 256 + threadIdx.x;
    if (idx >= BB * PP * RR) return;
    int r = idx % RR;
    float s = clasb[r];
#pragma unroll
    for (int c = 0; c < NCH; ++c) s += part[(size_t)c * (BB * PP * RR) + idx];
    out[idx] = s;
}

// ---------------- host ----------------
extern "C" void kernel_launch(void* const* d_in, const int* in_sizes, int n_in,
                              void* d_out, int out_size)
{
    const float* context   = (const float*)d_in[0];
    const float* attention = (const float*)d_in[1];
    const float* mmap      = (const float*)d_in[2];
    const float* emap      = (const float*)d_in[3];
    const int*   hts       = (const int*)d_in[4];
    const float* hW   = (const float*)d_in[5];
    const float* hb   = (const float*)d_in[6];
    const float* tW   = (const float*)d_in[7];
    const float* tb   = (const float*)d_in[8];
    const float* hcW  = (const float*)d_in[9];
    const float* hcb  = (const float*)d_in[10];
    const float* tcW  = (const float*)d_in[11];
    const float* tcb  = (const float*)d_in[12];
    const float* clasW = (const float*)d_in[13];
    const float* clasb = (const float*)d_in[14];
    float* out = (float*)d_out;

#define GETF(p, s) float* p; cudaGetSymbolAddress((void**)&p, s)
#define GETU(p, s) uint32_t* p; cudaGetSymbolAddress((void**)&p, s)
    GETF(att_sum, g_att_sum); GETF(mention, g_mention); GETF(tmp1, g_tmp1);
    GETF(matt, g_matt); GETF(eatt, g_eatt); GETF(emtok, g_emtok);
    GETF(entatt, g_entatt); GETF(hatt, g_hatt); GETF(tatt, g_tatt);
    GETU(ctxH2, g_ctxH2); GETU(ctxL2, g_ctxL2);
    GETU(hH2, g_hH2); GETU(hL2, g_hL2); GETU(tH2, g_tH2); GETU(tL2, g_tL2);
    GETU(cinfoH2, g_cinfoH2); GETU(cinfoL2, g_cinfoL2);
    GETF(hf, g_hf); GETF(tf, g_tf); GETF(part, g_part);
    GETU(hWf, g_hWf); GETU(tWf, g_tWf); GETU(hcWf, g_hcWf); GETU(tcWf, g_tcWf);
    GETU(ctxtH2, g_ctxtH2); GETU(ctxtL2, g_ctxtL2);
    uint2* Wt; cudaGetSymbolAddress((void**)&Wt, g_Wt);
#undef GETF
#undef GETU

    cudaFuncSetAttribute(clasmma_k, cudaFuncAttributeMaxDynamicSharedMemorySize, CLAS_SMEM);

    // 0+1) merged preprocessing + att_sum (R12 layout incl. clasW region)
    prep_k<<<14080, 256>>>(attention, att_sum, hW, tW, hcW, tcW,
                           hWf, tWf, hcWf, tcWf,
                           context, ctxtH2, ctxtL2, clasW, Wt);

    // 2+3) mention & tmp1 merged
    gemm23_k<<<dim3(12,1,8),256>>>(mmap, context, att_sum, mention, tmp1);

    // 4) mention_att (warp-per-output)
    matt_k<<<(BB*MM*MM*32 + 255)/256, 256>>>(tmp1, mmap, matt);

    // 5) entity_att (warp-per-output — the single change vs R12)
    eatt_k<<<(BB*EE*MM*32 + 255)/256, 256>>>(emap, matt, eatt);

    // 6) em_tok + normalize
    gemm_k<<<dim3(8,1,BB),256>>>(
        emap, mmap, emtok, EE, LL, MM,
        (long long)EE*MM, (long long)MM*LL, (long long)EE*LL);
    rownorm_k<<<BB*EE, 256>>>(emtok);

    // 7) ent_att (BM=32 tile)
    gemm32_k<<<dim3(8,1,BB*HH),256>>>(emtok, attention, entatt);

    // 8) per-pair vectors
    pair_att_k<<<BB*PP, 64>>>(hts, emap, eatt, hatt, tatt);
    ctx_k<<<BB*PP, 256>>>(hts, entatt, ctxH2, ctxL2);

    // 9) h, t merged (FFMA, fp16-split epilogue)
    ht9_k<<<dim3(12,8,2*BB),256>>>(tatt, hatt, mention, hH2, hL2, tH2, tL2);

    // 10) context_info (bf16x3 NT, fp16-split out)
    bf10_k<<<dim3(12,4,BB),256,BF_SMEM>>>(ctxH2, ctxL2, ctxtH2, ctxtL2,
                                          cinfoH2, cinfoL2);

    // 11+12) fused tanh-linears (fp16 2-term)
    hf1112_k<<<dim3(12,16,2),256,HF_SMEM>>>(
        hH2, hL2, tH2, tL2, hWf, tWf,
        cinfoH2, cinfoL2, hcWf, tcWf,
        hb, tb, hcb, tcb, hf, tf);

    // 13) classifier (fp16 2-term, smem-staged W)
    clasmma_k<<<dim3(BB*PP/128, NBK, 4), 256, CLAS_SMEM>>>(hf, tf, Wt, part);
    clas_red_k<<<(BB*PP*RR + 255)/256, 256>>>(part, clasb, out);
}

// round 15
// speedup vs baseline: 1.6605x; 1.0128x over previous
#include <cuda_runtime.h>
#include <cuda_bf16.h>
#include <cuda_fp16.h>
#include <cstdint>
#include <math.h>

#define BB 4
#define LL 512
#define DD 768
#define HH 12
#define MM 48
#define EE 32
#define PP 512
#define RR 97
#define NBK 12
#define NCH 48
#define KCLAS 49152
#define WT_U2 1792
#define WPAD 452
#define WPACK (DD*DD/2)

// ---------------- scratch ----------------
__device__ float g_att_sum[BB*LL*LL];
__device__ float g_mention[BB*MM*DD];
__device__ float g_tmp1[BB*MM*LL];
__device__ float g_matt[BB*MM*MM];
__device__ float g_eatt[BB*EE*MM];
__device__ float g_emtok[BB*EE*LL];
__device__ float g_entatt[BB*HH*EE*LL];
__device__ float g_hatt[BB*PP*MM];
__device__ float g_tatt[BB*PP*MM];
__device__ uint32_t g_ctxH2[BB*PP*LL/2];
__device__ uint32_t g_ctxL2[BB*PP*LL/2];
__device__ uint32_t g_hH2[BB*PP*DD/2];
__device__ uint32_t g_hL2[BB*PP*DD/2];
__device__ uint32_t g_tH2[BB*PP*DD/2];
__device__ uint32_t g_tL2[BB*PP*DD/2];
__device__ uint32_t g_cinfoH2[BB*PP*DD/2];
__device__ uint32_t g_cinfoL2[BB*PP*DD/2];
__device__ float g_hf[BB*PP*DD];
__device__ float g_tf[BB*PP*DD];
__device__ float g_part[NCH*BB*PP*RR];
__device__ uint32_t g_hWf[WPACK];
__device__ uint32_t g_tWf[WPACK];
__device__ uint32_t g_hcWf[WPACK];
__device__ uint32_t g_tcWf[WPACK];
__device__ uint32_t g_ctxtH2[BB*DD*LL/2];
__device__ uint32_t g_ctxtL2[BB*DD*LL/2];
__device__ uint2 g_Wt[NBK*64*WT_U2];

// ---------------- bf16 helpers ----------------
static __device__ __forceinline__ uint32_t pk2(float e0, float e1) {
    uint32_t r;
    asm("cvt.rn.bf16x2.f32 %0, %1, %2;" : "=r"(r) : "f"(e1), "f"(e0));
    return r;
}
static __device__ __forceinline__ void splitbf(float e0, float e1,
                                               uint32_t& H, uint32_t& L) {
    H = pk2(e0, e1);
    float h0 = __uint_as_float(H << 16);
    float h1 = __uint_as_float(H & 0xffff0000u);
    L = pk2(e0 - h0, e1 - h1);
}
static __device__ __forceinline__ void mma_bf(float* c, const uint32_t* a,
                                              uint32_t b0, uint32_t b1) {
    asm volatile(
        "mma.sync.aligned.m16n8k16.row.col.f32.bf16.bf16.f32 "
        "{%0,%1,%2,%3}, {%4,%5,%6,%7}, {%8,%9}, {%0,%1,%2,%3};"
        : "+f"(c[0]), "+f"(c[1]), "+f"(c[2]), "+f"(c[3])
        : "r"(a[0]), "r"(a[1]), "r"(a[2]), "r"(a[3]), "r"(b0), "r"(b1));
}

// ---------------- fp16 helpers ----------------
static __device__ __forceinline__ uint32_t pkh2(float e0, float e1) {
    __half2 h = __floats2half2_rn(e0, e1);
    return *(uint32_t*)&h;
}
static __device__ __forceinline__ void splitfp16(float e0, float e1,
                                                 uint32_t& H, uint32_t& L) {
    __half2 h = __floats2half2_rn(e0, e1);
    float2 hf = __half22float2(h);
    __half2 l = __floats2half2_rn(e0 - hf.x, e1 - hf.y);
    H = *(uint32_t*)&h;
    L = *(uint32_t*)&l;
}
static __device__ __forceinline__ void mma_fp16(float* c, const uint32_t* a,
                                                uint32_t b0, uint32_t b1) {
    asm volatile(
        "mma.sync.aligned.m16n8k16.row.col.f32.f16.f16.f32 "
        "{%0,%1,%2,%3}, {%4,%5,%6,%7}, {%8,%9}, {%0,%1,%2,%3};"
        : "+f"(c[0]), "+f"(c[1]), "+f"(c[2]), "+f"(c[3])
        : "r"(a[0]), "r"(a[1]), "r"(a[2]), "r"(a[3]), "r"(b0), "r"(b1));
}

// ---------------- merged preprocessing + att_sum ----------------
__global__ void prep_k(const float* __restrict__ att, float* __restrict__ att_sum,
                       const float* __restrict__ hW, const float* __restrict__ tW,
                       const float* __restrict__ hcW, const float* __restrict__ tcW,
                       uint32_t* __restrict__ hWf, uint32_t* __restrict__ tWf,
                       uint32_t* __restrict__ hcWf, uint32_t* __restrict__ tcWf,
                       const float* __restrict__ context,
                       uint32_t* __restrict__ ctH, uint32_t* __restrict__ ctL,
                       const float* __restrict__ clasW, uint2* __restrict__ Wt)
{
    int blk = blockIdx.x, tid = threadIdx.x;
    if (blk < 1024) {
        int idx = blk * 256 + tid;
        int b  = idx >> 16;
        int lm = idx & (LL*LL/4 - 1);
        const float4* p = (const float4*)(att + (size_t)b*HH*LL*LL) + lm;
        float4 s = make_float4(0.f, 0.f, 0.f, 0.f);
#pragma unroll
        for (int h = 0; h < HH; ++h) {
            float4 v = p[(size_t)h*(LL*LL/4)];
            s.x += v.x; s.y += v.y; s.z += v.z; s.w += v.w;
        }
        ((float4*)att_sum)[idx] = s;
    } else if (blk < 5632) {
        int idx = (blk - 1024) * 256 + tid;
        int w = idx / WPACK, j = idx % WPACK;
        const float* src = (w == 0) ? hW : (w == 1) ? tW : (w == 2) ? hcW : tcW;
        uint32_t* dst = (w == 0) ? hWf : (w == 1) ? tWf : (w == 2) ? hcWf : tcWf;
        float2 v = ((const float2*)src)[j];
        dst[j] = pkh2(v.x, v.y);
    } else if (blk < 8704) {
        int idx = (blk - 5632) * 256 + tid;
        int lp = idx & 255;
        int bd = idx >> 8;
        int d = bd % DD, b = bd / DD;
        float e0 = context[((size_t)b*LL + 2*lp)     * DD + d];
        float e1 = context[((size_t)b*LL + 2*lp + 1) * DD + d];
        uint32_t h, l; splitbf(e0, e1, h, l);
        ctH[idx] = h; ctL[idx] = l;
    } else {
        int idx = (blk - 8704) * 256 + tid;
        int fi = idx % WT_U2;
        int ni = idx / WT_U2;
        int i = ni & 63, n = ni >> 6;
        int r  = fi % 112;
        int s  = (fi / 112) & 3;
        int kq = fi / 448;
        int j0 = s*16 + 2*kq;
        float w00 = 0.f, w01 = 0.f, w10 = 0.f, w11 = 0.f;
        if (r < RR) {
            const float* base = clasW + (size_t)r*KCLAS + (size_t)n*4096 + i*64;
            w00 = base[j0];     w01 = base[j0 + 1];
            w10 = base[j0 + 8]; w11 = base[j0 + 9];
        }
        uint2 o;
        o.x = pkh2(w00, w01);
        o.y = pkh2(w10, w11);
        Wt[idx] = o;
    }
}

// ---------------- small kernels ----------------
__global__ void rownorm_k(float* __restrict__ x)
{
    int row = blockIdx.x;
    float* p = x + (size_t)row * LL;
    int t = threadIdx.x;
    float v0 = p[t], v1 = p[t + 256];
    __shared__ float sm[256];
    sm[t] = v0 + v1; __syncthreads();
    for (int o = 128; o > 0; o >>= 1) { if (t < o) sm[t] += sm[t + o]; __syncthreads(); }
    float inv = 1.f / (sm[0] + 1e-30f);
    p[t] = v0 * inv; p[t + 256] = v1 * inv;
}

__global__ void pair_att_k(const int* __restrict__ hts,
                           const float* __restrict__ emap,
                           const float* __restrict__ eatt,
                           float* __restrict__ hattO, float* __restrict__ tattO)
{
    int bp = blockIdx.x;
    int b  = bp >> 9;
    int hi = hts[(size_t)bp*2], ti = hts[(size_t)bp*2 + 1];
    float mask = (hi + ti != 0) ? 1.f : 0.f;
    int t = threadIdx.x;
    float ha = 0.f, ta = 0.f;
    if (t < MM) {
        float hm = emap[((size_t)b*EE + hi)*MM + t] * mask;
        float tm = emap[((size_t)b*EE + ti)*MM + t] * mask;
        ha = eatt[((size_t)b*EE + hi)*MM + t] * tm;
        ta = eatt[((size_t)b*EE + ti)*MM + t] * hm;
    }
    __shared__ float smh[64], smt[64];
    smh[t] = ha; smt[t] = ta; __syncthreads();
    for (int o = 32; o > 0; o >>= 1) {
        if (t < o) { smh[t] += smh[t + o]; smt[t] += smt[t + o]; }
        __syncthreads();
    }
    float invh = 1.f / (smh[0] + 1e-30f);
    float invt = 1.f / (smt[0] + 1e-30f);
    if (t < MM) {
        hattO[(size_t)bp*MM + t] = ha * invh;
        tattO[(size_t)bp*MM + t] = ta * invt;
    }
}

__global__ void ctx_k(const int* __restrict__ hts,
                      const float* __restrict__ entatt,
                      uint32_t* __restrict__ ctxH2, uint32_t* __restrict__ ctxL2)
{
    int bp = blockIdx.x; int b = bp >> 9;
    int hi = hts[(size_t)bp*2], ti = hts[(size_t)bp*2 + 1];
    float mask = (hi + ti != 0) ? 1.f : 0.f;
    int t = threadIdx.x;
    const float* base = entatt + (size_t)b*HH*EE*LL;
    float v0 = 0.f, v1 = 0.f;
#pragma unroll
    for (int h = 0; h < HH; ++h) {
        const float2* ph = (const float2*)(base + ((size_t)h*EE + hi)*LL);
        const float2* pt = (const float2*)(base + ((size_t)h*EE + ti)*LL);
        float2 x = ph[t], y = pt[t];
        v0 += x.x * y.x;
        v1 += x.y * y.y;
    }
    __shared__ float sm[256];
    sm[t] = v0 + v1; __syncthreads();
    for (int o = 128; o > 0; o >>= 1) { if (t < o) sm[t] += sm[t + o]; __syncthreads(); }
    float inv = mask / (sm[0] + 1e-30f);
    uint32_t H, L; splitbf(v0 * inv, v1 * inv, H, L);
    ctxH2[(size_t)bp*(LL/2) + t] = H;
    ctxL2[(size_t)bp*(LL/2) + t] = L;
}

__global__ void matt_k(const float* __restrict__ tmp1, const float* __restrict__ mmap,
                       float* __restrict__ matt)
{
    int gw = (blockIdx.x * 256 + threadIdx.x) >> 5;
    if (gw >= BB*MM*MM) return;
    int lane = threadIdx.x & 31;
    int b = gw / (MM*MM);
    int rem = gw % (MM*MM);
    int m = rem / MM, j = rem % MM;
    const float4* a = (const float4*)(tmp1 + ((size_t)b*MM + m)*LL);
    const float4* c = (const float4*)(mmap + ((size_t)b*MM + j)*LL);
    float s = 0.f;
#pragma unroll
    for (int k = lane; k < 128; k += 32) {
        float4 x = a[k], y = c[k];
        s += x.x*y.x + x.y*y.y + x.z*y.z + x.w*y.w;
    }
#pragma unroll
    for (int o = 16; o; o >>= 1) s += __shfl_xor_sync(0xffffffffu, s, o);
    if (lane == 0) matt[gw] = s;
}

__global__ void eatt_k(const float* __restrict__ emap, const float* __restrict__ matt,
                       float* __restrict__ eatt)
{
    int gw = (blockIdx.x * 256 + threadIdx.x) >> 5;
    if (gw >= BB*EE*MM) return;
    int lane = threadIdx.x & 31;
    int b = gw / (EE*MM);
    int rem = gw % (EE*MM);
    int e = rem / MM, j = rem % MM;
    const float* em = emap + ((size_t)b*EE + e)*MM;
    const float* mt = matt + (size_t)b*MM*MM + j;
    float s = em[lane] * mt[lane*MM];
    if (lane < 16) s += em[lane + 32] * mt[(lane + 32)*MM];
#pragma unroll
    for (int o = 16; o; o >>= 1) s += __shfl_xor_sync(0xffffffffu, s, o);
    if (lane == 0) eatt[gw] = s;
}

// ---------------- generic FFMA GEMM (em_tok only) ----------------
__global__ __launch_bounds__(256)
void gemm_k(const float* __restrict__ Ag, const float* __restrict__ Bg,
            float* __restrict__ Cg, int M, int N, int K,
            long long sA, long long sB, long long sC)
{
    const int BM = 64, BN = 64, BK = 16;
    int z = blockIdx.z;
    const float* A  = Ag + (long long)z * sA;
    const float* Bp = Bg + (long long)z * sB;
    float* C = Cg + (long long)z * sC;
    int row0 = blockIdx.y * BM;
    int col0 = blockIdx.x * BN;

    __shared__ float As[BK][BM + 1];
    __shared__ float Bs[BK][BN + 1];

    int tid = threadIdx.x;
    int tx = tid & 15, ty = tid >> 4;
    float acc[4][4] = {};

    for (int k0 = 0; k0 < K; k0 += BK) {
#pragma unroll
        for (int r = 0; r < 4; ++r) {
            int idx = tid + r * 256;
            int m = idx >> 4, k = idx & 15;
            float v = 0.f;
            if (row0 + m < M) v = A[(size_t)(row0 + m) * K + k0 + k];
            As[k][m] = v;
        }
#pragma unroll
        for (int r = 0; r < 4; ++r) {
            int idx = tid + r * 256;
            int k = idx >> 6, n = idx & 63;
            float v = 0.f;
            if (col0 + n < N) v = Bp[(size_t)(k0 + k) * N + col0 + n];
            Bs[k][n] = v;
        }
        __syncthreads();
#pragma unroll
        for (int k = 0; k < BK; ++k) {
            float a[4], bb[4];
#pragma unroll
            for (int i = 0; i < 4; ++i) a[i]  = As[k][ty * 4 + i];
#pragma unroll
            for (int j = 0; j < 4; ++j) bb[j] = Bs[k][tx * 4 + j];
#pragma unroll
            for (int i = 0; i < 4; ++i)
#pragma unroll
                for (int j = 0; j < 4; ++j) acc[i][j] += a[i] * bb[j];
        }
        __syncthreads();
    }

#pragma unroll
    for (int i = 0; i < 4; ++i) {
        int m = row0 + ty * 4 + i;
        if (m >= M) continue;
#pragma unroll
        for (int j = 0; j < 4; ++j) {
            int n = col0 + tx * 4 + j;
            if (n >= N) continue;
            C[(size_t)m * N + n] = acc[i][j];
        }
    }
}

// merged steps 2+3
__global__ __launch_bounds__(256)
void gemm23_k(const float* __restrict__ mmap, const float* __restrict__ context,
              const float* __restrict__ att_sum,
              float* __restrict__ mention, float* __restrict__ tmp1)
{
    const int BN = 64, BK = 16;
    int zz = blockIdx.z;
    int b = zz & 3, sel = zz >> 2;
    if (sel && blockIdx.x >= 8) return;
    int N = sel ? LL : DD;
    const float* A  = mmap + (size_t)b*MM*LL;
    const float* Bp = sel ? (att_sum + (size_t)b*LL*LL) : (context + (size_t)b*LL*DD);
    float* C = sel ? (tmp1 + (size_t)b*MM*LL) : (mention + (size_t)b*MM*DD);
    int col0 = blockIdx.x * BN;

    __shared__ float As[BK][65];
    __shared__ float Bs[BK][BN + 1];

    int tid = threadIdx.x;
    int tx = tid & 15, ty = tid >> 4;
    float acc[4][4] = {};

    for (int k0 = 0; k0 < LL; k0 += BK) {
#pragma unroll
        for (int r = 0; r < 4; ++r) {
            int idx = tid + r * 256;
            int m = idx >> 4, k = idx & 15;
            As[k][m] = (m < MM) ? A[(size_t)m * LL + k0 + k] : 0.f;
        }
#pragma unroll
        for (int r = 0; r < 4; ++r) {
            int idx = tid + r * 256;
            int k = idx >> 6, n = idx & 63;
            Bs[k][n] = Bp[(size_t)(k0 + k) * N + col0 + n];
        }
        __syncthreads();
#pragma unroll
        for (int k = 0; k < BK; ++k) {
            float a[4], bb[4];
#pragma unroll
            for (int i = 0; i < 4; ++i) a[i]  = As[k][ty * 4 + i];
#pragma unroll
            for (int j = 0; j < 4; ++j) bb[j] = Bs[k][tx * 4 + j];
#pragma unroll
            for (int i = 0; i < 4; ++i)
#pragma unroll
                for (int j = 0; j < 4; ++j) acc[i][j] += a[i] * bb[j];
        }
        __syncthreads();
    }

#pragma unroll
    for (int i = 0; i < 4; ++i) {
        int m = ty * 4 + i;
        if (m >= MM) continue;
#pragma unroll
        for (int j = 0; j < 4; ++j)
            C[(size_t)m * N + col0 + tx * 4 + j] = acc[i][j];
    }
}

// step 7: ent_att, BM=32 tile
__global__ __launch_bounds__(256)
void gemm32_k(const float* __restrict__ emtok, const float* __restrict__ att,
              float* __restrict__ entatt)
{
    int z = blockIdx.z;
    const float* A  = emtok + (size_t)(z / HH) * EE * LL;
    const float* Bp = att + (size_t)z * LL * LL;
    float* C = entatt + (size_t)z * EE * LL;
    int col0 = blockIdx.x * 64;

    __shared__ float As[16][34];
    __shared__ float Bs[16][68];

    int tid = threadIdx.x;
    int tx = tid & 15, ty = tid >> 4;
    float acc[2][4] = {};

    for (int k0 = 0; k0 < LL; k0 += 16) {
#pragma unroll
        for (int r = 0; r < 2; ++r) {
            int idx = tid + r * 256;
            int m = idx >> 4, k = idx & 15;
            As[k][m] = A[(size_t)m * LL + k0 + k];
        }
#pragma unroll
        for (int r = 0; r < 4; ++r) {
            int idx = tid + r * 256;
            int k = idx >> 6, n = idx & 63;
            Bs[k][n] = Bp[(size_t)(k0 + k) * LL + col0 + n];
        }
        __syncthreads();
#pragma unroll
        for (int k = 0; k < 16; ++k) {
            float2 a = *(const float2*)&As[k][ty * 2];
            float4 bv = *(const float4*)&Bs[k][tx * 4];
            acc[0][0] += a.x * bv.x; acc[0][1] += a.x * bv.y;
            acc[0][2] += a.x * bv.z; acc[0][3] += a.x * bv.w;
            acc[1][0] += a.y * bv.x; acc[1][1] += a.y * bv.y;
            acc[1][2] += a.y * bv.z; acc[1][3] += a.y * bv.w;
        }
        __syncthreads();
    }

#pragma unroll
    for (int i = 0; i < 2; ++i)
#pragma unroll
        for (int j = 0; j < 4; ++j)
            C[(size_t)(ty*2 + i) * LL + col0 + tx*4 + j] = acc[i][j];
}

// step 9 merged, fp16-split epilogue
__global__ __launch_bounds__(256)
void ht9_k(const float* __restrict__ tatt, const float* __restrict__ hatt,
           const float* __restrict__ mention,
           uint32_t* __restrict__ hH2, uint32_t* __restrict__ hL2,
           uint32_t* __restrict__ tH2, uint32_t* __restrict__ tL2)
{
    const int BM = 64, BN = 64, BK = 16;
    int zz = blockIdx.z;
    int b = zz & (BB - 1), sel = zz >> 2;
    const float* A  = (sel ? hatt : tatt) + (size_t)b * PP * MM;
    const float* Bp = mention + (size_t)b * MM * DD;
    uint32_t* CH = (sel ? tH2 : hH2) + (size_t)b * PP * (DD/2);
    uint32_t* CL = (sel ? tL2 : hL2) + (size_t)b * PP * (DD/2);
    int row0 = blockIdx.y * BM;
    int col0 = blockIdx.x * BN;

    __shared__ float As[BK][BM + 1];
    __shared__ float Bs[BK][BN + 1];

    int tid = threadIdx.x;
    int tx = tid & 15, ty = tid >> 4;
    float acc[4][4] = {};

    for (int k0 = 0; k0 < MM; k0 += BK) {
#pragma unroll
        for (int r = 0; r < 4; ++r) {
            int idx = tid + r * 256;
            int m = idx >> 4, k = idx & 15;
            As[k][m] = A[(size_t)(row0 + m) * MM + k0 + k];
        }
#pragma unroll
        for (int r = 0; r < 4; ++r) {
            int idx = tid + r * 256;
            int k = idx >> 6, n = idx & 63;
            Bs[k][n] = Bp[(size_t)(k0 + k) * DD + col0 + n];
        }
        __syncthreads();
#pragma unroll
        for (int k = 0; k < BK; ++k) {
            float a[4], bb[4];
#pragma unroll
            for (int i = 0; i < 4; ++i) a[i]  = As[k][ty * 4 + i];
#pragma unroll
            for (int j = 0; j < 4; ++j) bb[j] = Bs[k][tx * 4 + j];
#pragma unroll
            for (int i = 0; i < 4; ++i)
#pragma unroll
                for (int j = 0; j < 4; ++j) acc[i][j] += a[i] * bb[j];
        }
        __syncthreads();
    }

#pragma unroll
    for (int i = 0; i < 4; ++i) {
        int m = row0 + ty * 4 + i;
        int np = (col0 + tx * 4) >> 1;
        uint32_t H, L;
        splitfp16(acc[i][0], acc[i][1], H, L);
        CH[(size_t)m * (DD/2) + np]     = H;
        CL[(size_t)m * (DD/2) + np]     = L;
        splitfp16(acc[i][2], acc[i][3], H, L);
        CH[(size_t)m * (DD/2) + np + 1] = H;
        CL[(size_t)m * (DD/2) + np + 1] = L;
    }
}

// ---------------- bf16x3 NT GEMM: cinfo (fp16-split output) ----------------
#define BF_SMEM ((128*20 + 64*20) * 2 * 4)
__global__ __launch_bounds__(256)
void bf10_k(const uint32_t* __restrict__ AHg, const uint32_t* __restrict__ ALg,
            const uint32_t* __restrict__ BHg, const uint32_t* __restrict__ BLg,
            uint32_t* __restrict__ CH2g, uint32_t* __restrict__ CL2g)
{
    extern __shared__ uint32_t usm[];
    uint32_t* AsH = usm;
    uint32_t* AsL = AsH + 128*20;
    uint32_t* BsH = AsL + 128*20;
    uint32_t* BsL = BsH + 64*20;

    int z = blockIdx.z;
    const int KP = LL/2, N = DD;
    const uint32_t* AH = AHg + (size_t)z*PP*KP;
    const uint32_t* AL = ALg + (size_t)z*PP*KP;
    const uint32_t* BH = BHg + (size_t)z*DD*KP;
    const uint32_t* BL = BLg + (size_t)z*DD*KP;
    uint32_t* CH2 = CH2g + (size_t)z*PP*(DD/2);
    uint32_t* CL2 = CL2g + (size_t)z*PP*(DD/2);
    int row0 = blockIdx.y * 128, col0 = blockIdx.x * 64;
    int tid = threadIdx.x, lane = tid & 31, wid = tid >> 5;
    int m_off = (wid & 3) * 32, n_off = (wid >> 2) * 32;
    int g = lane >> 2, kq = lane & 3;

    float acc[2][4][4];
#pragma unroll
    for (int a = 0; a < 2; ++a)
#pragma unroll
        for (int b = 0; b < 4; ++b)
#pragma unroll
            for (int c = 0; c < 4; ++c) acc[a][b][c] = 0.f;

    for (int kp0 = 0; kp0 < KP; kp0 += 16) {
        __syncthreads();
#pragma unroll
        for (int r2 = 0; r2 < 2; ++r2) {
            int slot = tid + r2 * 256;
            int m = slot >> 2, q = slot & 3;
            *(uint4*)(AsH + m*20 + q*4) =
                *(const uint4*)(AH + (size_t)(row0 + m)*KP + kp0 + q*4);
            *(uint4*)(AsL + m*20 + q*4) =
                *(const uint4*)(AL + (size_t)(row0 + m)*KP + kp0 + q*4);
        }
        {
            int n = tid >> 2, q = tid & 3;
            *(uint4*)(BsH + n*20 + q*4) =
                *(const uint4*)(BH + (size_t)(col0 + n)*KP + kp0 + q*4);
            *(uint4*)(BsL + n*20 + q*4) =
                *(const uint4*)(BL + (size_t)(col0 + n)*KP + kp0 + q*4);
        }
        __syncthreads();
#pragma unroll
        for (int st = 0; st < 2; ++st) {
            int pb = st*8 + kq;
            uint32_t aH[2][4], aL[2][4];
#pragma unroll
            for (int mt = 0; mt < 2; ++mt) {
                int mr = m_off + mt*16 + g;
                aH[mt][0] = AsH[mr*20 + pb];       aL[mt][0] = AsL[mr*20 + pb];
                aH[mt][1] = AsH[(mr+8)*20 + pb];   aL[mt][1] = AsL[(mr+8)*20 + pb];
                aH[mt][2] = AsH[mr*20 + pb + 4];   aL[mt][2] = AsL[mr*20 + pb + 4];
                aH[mt][3] = AsH[(mr+8)*20 + pb+4]; aL[mt][3] = AsL[(mr+8)*20 + pb+4];
            }
#pragma unroll
            for (int nt = 0; nt < 4; ++nt) {
                int nr = n_off + nt*8 + g;
                uint32_t bH0 = BsH[nr*20 + pb], bH1 = BsH[nr*20 + pb + 4];
                uint32_t bL0 = BsL[nr*20 + pb], bL1 = BsL[nr*20 + pb + 4];
#pragma unroll
                for (int mt = 0; mt < 2; ++mt) {
                    mma_bf(acc[mt][nt], aH[mt], bH0, bH1);
                    mma_bf(acc[mt][nt], aH[mt], bL0, bL1);
                    mma_bf(acc[mt][nt], aL[mt], bH0, bH1);
                }
            }
        }
    }

#pragma unroll
    for (int mt = 0; mt < 2; ++mt) {
#pragma unroll
        for (int nt = 0; nt < 4; ++nt) {
            int mr = row0 + m_off + mt*16 + g;
            int nc = col0 + n_off + nt*8 + 2*kq;
            int np = nc >> 1;
            uint32_t H, L;
            splitfp16(acc[mt][nt][0], acc[mt][nt][1], H, L);
            CH2[(size_t)mr*(N/2) + np] = H; CL2[(size_t)mr*(N/2) + np] = L;
            splitfp16(acc[mt][nt][2], acc[mt][nt][3], H, L);
            CH2[(size_t)(mr+8)*(N/2) + np] = H; CL2[(size_t)(mr+8)*(N/2) + np] = L;
        }
    }
}

// ---------------- fp16 2-term fused tanh-linears ----------------
#define HF_SMEM ((128*20*2 + 64*20*2) * 4)
__global__ __launch_bounds__(256)
void hf1112_k(const uint32_t* __restrict__ hH2, const uint32_t* __restrict__ hL2,
              const uint32_t* __restrict__ tH2, const uint32_t* __restrict__ tL2,
              const uint32_t* __restrict__ hWf, const uint32_t* __restrict__ tWf,
              const uint32_t* __restrict__ cH2, const uint32_t* __restrict__ cL2,
              const uint32_t* __restrict__ hcWf, const uint32_t* __restrict__ tcWf,
              const float* __restrict__ hb, const float* __restrict__ tb,
              const float* __restrict__ hcb, const float* __restrict__ tcb,
              float* __restrict__ hf, float* __restrict__ tf)
{
    extern __shared__ uint32_t usm[];
    uint32_t* AsH = usm;
    uint32_t* AsL = AsH + 128*20;
    uint32_t* Bs  = AsL + 128*20;

    int zsel = blockIdx.z;
    const uint32_t* A1H = zsel ? tH2 : hH2;
    const uint32_t* A1L = zsel ? tL2 : hL2;
    const uint32_t* B1  = zsel ? tWf : hWf;
    const uint32_t* B2  = zsel ? tcWf : hcWf;
    const float* bias1 = zsel ? tb : hb;
    const float* bias2 = zsel ? tcb : hcb;
    float* C = zsel ? tf : hf;

    const int KP = DD/2, N = DD;
    int row0 = blockIdx.y * 128, col0 = blockIdx.x * 64;
    int tid = threadIdx.x, lane = tid & 31, wid = tid >> 5;
    int m_off = (wid & 3) * 32, n_off = (wid >> 2) * 32;
    int g = lane >> 2, kq = lane & 3;

    float acc[2][4][4];
#pragma unroll
    for (int a = 0; a < 2; ++a)
#pragma unroll
        for (int b = 0; b < 4; ++b)
#pragma unroll
            for (int c = 0; c < 4; ++c) acc[a][b][c] = 0.f;

    for (int pass = 0; pass < 2; ++pass) {
        const uint32_t* AH = pass ? cH2 : A1H;
        const uint32_t* AL = pass ? cL2 : A1L;
        const uint32_t* B  = pass ? B2  : B1;
        for (int kp0 = 0; kp0 < KP; kp0 += 16) {
            __syncthreads();
#pragma unroll
            for (int r2 = 0; r2 < 2; ++r2) {
                int slot = tid + r2 * 256;
                int m = slot >> 2, q = slot & 3;
                *(uint4*)(AsH + m*20 + q*4) =
                    *(const uint4*)(AH + (size_t)(row0 + m)*KP + kp0 + q*4);
                *(uint4*)(AsL + m*20 + q*4) =
                    *(const uint4*)(AL + (size_t)(row0 + m)*KP + kp0 + q*4);
            }
            {
                int n = tid >> 2, q = tid & 3;
                *(uint4*)(Bs + n*20 + q*4) =
                    *(const uint4*)(B + (size_t)(col0 + n)*KP + kp0 + q*4);
            }
            __syncthreads();
#pragma unroll
            for (int st = 0; st < 2; ++st) {
                int pb = st*8 + kq;
                uint32_t aH[2][4], aL[2][4];
#pragma unroll
                for (int mt = 0; mt < 2; ++mt) {
                    int mr = m_off + mt*16 + g;
                    aH[mt][0] = AsH[mr*20 + pb];       aL[mt][0] = AsL[mr*20 + pb];
                    aH[mt][1] = AsH[(mr+8)*20 + pb];   aL[mt][1] = AsL[(mr+8)*20 + pb];
                    aH[mt][2] = AsH[mr*20 + pb + 4];   aL[mt][2] = AsL[mr*20 + pb + 4];
                    aH[mt][3] = AsH[(mr+8)*20 + pb+4]; aL[mt][3] = AsL[(mr+8)*20 + pb+4];
                }
#pragma unroll
                for (int nt = 0; nt < 4; ++nt) {
                    int nr = n_off + nt*8 + g;
                    uint32_t b0 = Bs[nr*20 + pb], b1 = Bs[nr*20 + pb + 4];
#pragma unroll
                    for (int mt = 0; mt < 2; ++mt) {
                        mma_fp16(acc[mt][nt], aH[mt], b0, b1);
                        mma_fp16(acc[mt][nt], aL[mt], b0, b1);
                    }
                }
            }
        }
    }

#pragma unroll
    for (int mt = 0; mt < 2; ++mt) {
#pragma unroll
        for (int nt = 0; nt < 4; ++nt) {
            int mr = row0 + m_off + mt*16 + g;
            int nc = col0 + n_off + nt*8 + 2*kq;
            float b0 = bias1[nc]   + bias2[nc];
            float b1 = bias1[nc+1] + bias2[nc+1];
            C[(size_t)mr * N + nc]       = tanhf(acc[mt][nt][0] + b0);
            C[(size_t)mr * N + nc + 1]   = tanhf(acc[mt][nt][1] + b1);
            C[(size_t)(mr+8) * N + nc]   = tanhf(acc[mt][nt][2] + b0);
            C[(size_t)(mr+8) * N + nc+1] = tanhf(acc[mt][nt][3] + b1);
        }
    }
}

// ------- classifier: fp16 2-term, single-buffer smem W, 2 CTAs/SM -----------
#define CLAS_SMEM (128*17*4 + 2*128*33*4 + 4*WPAD*8)
__global__ __launch_bounds__(256, 2)
void clasmma_k(const float* __restrict__ Hf, const float* __restrict__ Tf,
               const uint2* __restrict__ Wt, float* __restrict__ part)
{
    extern __shared__ char smraw[];
    float*    hs  = (float*)smraw;
    uint32_t* tsH = (uint32_t*)(hs + 128*17);
    uint32_t* tsL = tsH + 128*33;
    uint2*    ws  = (uint2*)(tsL + 128*33);   // [4*WPAD] single buffer

    const int n = blockIdx.y, z = blockIdx.z;
    const int p0 = blockIdx.x * 128;
    int tid = threadIdx.x, lane = tid & 31, wid = tid >> 5;
    int pbase = (wid & 3) * 32, nbase = (wid >> 2) * 56;
    int g = lane >> 2, kq = lane & 3;

    for (int v = tid; v < 128*32; v += 256) {
        int p = v >> 5, q = v & 31;
        if (q < 16)
            hs[p*17 + q] = Hf[(size_t)(p0 + p)*DD + n*64 + z*16 + q];
        float t0 = Tf[(size_t)(p0 + p)*DD + n*64 + 2*q];
        float t1 = Tf[(size_t)(p0 + p)*DD + n*64 + 2*q + 1];
        uint32_t H, L; splitfp16(t0, t1, H, L);
        tsH[p*33 + q] = H; tsL[p*33 + q] = L;
    }
    __syncthreads();

    uint32_t tAH[2][4][4], tAL[2][4][4];
#pragma unroll
    for (int mt = 0; mt < 2; ++mt) {
        int pr = pbase + mt*16 + g;
#pragma unroll
        for (int s = 0; s < 4; ++s) {
            int pp = s*8 + kq;
            tAH[mt][s][0] = tsH[pr*33 + pp];       tAL[mt][s][0] = tsL[pr*33 + pp];
            tAH[mt][s][1] = tsH[(pr+8)*33 + pp];   tAL[mt][s][1] = tsL[(pr+8)*33 + pp];
            tAH[mt][s][2] = tsH[pr*33 + pp + 4];   tAL[mt][s][2] = tsL[pr*33 + pp + 4];
            tAH[mt][s][3] = tsH[(pr+8)*33 + pp+4]; tAL[mt][s][3] = tsL[(pr+8)*33 + pp+4];
        }
    }

    float acc[2][7][4];
#pragma unroll
    for (int a = 0; a < 2; ++a)
#pragma unroll
        for (int b = 0; b < 7; ++b)
#pragma unroll
            for (int c = 0; c < 4; ++c) acc[a][b][c] = 0.f;

    for (int ii = 0; ii < 16; ++ii) {
        // stage W(ii) cooperatively (single buffer, two barriers)
        {
            const uint2* Wg = Wt + (size_t)(n*64 + z*16 + ii) * WT_U2;
            uint2 tmpw[7];
#pragma unroll
            for (int w = 0; w < 7; ++w) tmpw[w] = Wg[tid + w*256];
            __syncthreads();   // prior compute done reading ws
#pragma unroll
            for (int w = 0; w < 7; ++w) {
                int v = tid + w*256;
                int kq2 = v / 448, rem = v - kq2*448;
                ws[kq2*WPAD + rem] = tmpw[w];
            }
            __syncthreads();
        }

        float hv0[2], hv1[2];
#pragma unroll
        for (int mt = 0; mt < 2; ++mt) {
            int pr = pbase + mt*16 + g;
            hv0[mt] = hs[pr*17 + ii];
            hv1[mt] = hs[(pr+8)*17 + ii];
        }

        // nt outer, s inner: tmp shrinks to [2][4] regs; per-(mt,nt) the
        // s-accumulation order is unchanged -> bit-identical results
#pragma unroll
        for (int nt = 0; nt < 7; ++nt) {
            int r = nbase + nt*8 + g;
            float tmp2[2][4];
#pragma unroll
            for (int a = 0; a < 2; ++a)
#pragma unroll
                for (int c = 0; c < 4; ++c) tmp2[a][c] = 0.f;
#pragma unroll
            for (int s = 0; s < 4; ++s) {
                uint2 w2 = ws[kq*WPAD + s*112 + r];
#pragma unroll
                for (int mt = 0; mt < 2; ++mt) {
                    mma_fp16(tmp2[mt], tAH[mt][s], w2.x, w2.y);
                    mma_fp16(tmp2[mt], tAL[mt][s], w2.x, w2.y);
                }
            }
#pragma unroll
            for (int mt = 0; mt < 2; ++mt) {
                acc[mt][nt][0] += hv0[mt] * tmp2[mt][0];
                acc[mt][nt][1] += hv0[mt] * tmp2[mt][1];
                acc[mt][nt][2] += hv1[mt] * tmp2[mt][2];
                acc[mt][nt][3] += hv1[mt] * tmp2[mt][3];
            }
        }
    }

    int chunk = n*4 + z;
    float* po = part + (size_t)chunk * (BB*PP*RR);
#pragma unroll
    for (int mt = 0; mt < 2; ++mt) {
#pragma unroll
        for (int nt = 0; nt < 7; ++nt) {
            int p = p0 + pbase + mt*16 + g;
            int r = nbase + nt*8 + 2*kq;
            if (r < RR)   po[(size_t)p*RR + r]       = acc[mt][nt][0];
            if (r+1 < RR) po[(size_t)p*RR + r + 1]   = acc[mt][nt][1];
            if (r < RR)   po[(size_t)(p+8)*RR + r]   = acc[mt][nt][2];
            if (r+1 < RR) po[(size_t)(p+8)*RR + r+1] = acc[mt][nt][3];
        }
    }
}

__global__ void clas_red_k(const float* __restrict__ part,
                           const float* __restrict__ clasb,
                           float* __restrict__ out)
{
    int idx = blockIdx.x * 256 + threadIdx.x;
    if (idx >= BB * PP * RR) return;
    int r = idx % RR;
    float s = clasb[r];
#pragma unroll
    for (int c = 0; c < NCH; ++c) s += part[(size_t)c * (BB * PP * RR) + idx];
    out[idx] = s;
}

// ---------------- host ----------------
extern "C" void kernel_launch(void* const* d_in, const int* in_sizes, int n_in,
                              void* d_out, int out_size)
{
    const float* context   = (const float*)d_in[0];
    const float* attention = (const float*)d_in[1];
    const float* mmap      = (const float*)d_in[2];
    const float* emap      = (const float*)d_in[3];
    const int*   hts       = (const int*)d_in[4];
    const float* hW   = (const float*)d_in[5];
    const float* hb   = (const float*)d_in[6];
    const float* tW   = (const float*)d_in[7];
    const float* tb   = (const float*)d_in[8];
    const float* hcW  = (const float*)d_in[9];
    const float* hcb  = (const float*)d_in[10];
    const float* tcW  = (const float*)d_in[11];
    const float* tcb  = (const float*)d_in[12];
    const float* clasW = (const float*)d_in[13];
    const float* clasb = (const float*)d_in[14];
    float* out = (float*)d_out;

#define GETF(p, s) float* p; cudaGetSymbolAddress((void**)&p, s)
#define GETU(p, s) uint32_t* p; cudaGetSymbolAddress((void**)&p, s)
    GETF(att_sum, g_att_sum); GETF(mention, g_mention); GETF(tmp1, g_tmp1);
    GETF(matt, g_matt); GETF(eatt, g_eatt); GETF(emtok, g_emtok);
    GETF(entatt, g_entatt); GETF(hatt, g_hatt); GETF(tatt, g_tatt);
    GETU(ctxH2, g_ctxH2); GETU(ctxL2, g_ctxL2);
    GETU(hH2, g_hH2); GETU(hL2, g_hL2); GETU(tH2, g_tH2); GETU(tL2, g_tL2);
    GETU(cinfoH2, g_cinfoH2); GETU(cinfoL2, g_cinfoL2);
    GETF(hf, g_hf); GETF(tf, g_tf); GETF(part, g_part);
    GETU(hWf, g_hWf); GETU(tWf, g_tWf); GETU(hcWf, g_hcWf); GETU(tcWf, g_tcWf);
    GETU(ctxtH2, g_ctxtH2); GETU(ctxtL2, g_ctxtL2);
    uint2* Wt; cudaGetSymbolAddress((void**)&Wt, g_Wt);
#undef GETF
#undef GETU

    cudaFuncSetAttribute(clasmma_k, cudaFuncAttributeMaxDynamicSharedMemorySize, CLAS_SMEM);

    // 0+1) merged preprocessing + att_sum
    prep_k<<<14080, 256>>>(attention, att_sum, hW, tW, hcW, tcW,
                           hWf, tWf, hcWf, tcWf,
                           context, ctxtH2, ctxtL2, clasW, Wt);

    // 2+3) mention & tmp1 merged
    gemm23_k<<<dim3(12,1,8),256>>>(mmap, context, att_sum, mention, tmp1);

    // 4) mention_att
    matt_k<<<(BB*MM*MM*32 + 255)/256, 256>>>(tmp1, mmap, matt);

    // 5) entity_att
    eatt_k<<<(BB*EE*MM*32 + 255)/256, 256>>>(emap, matt, eatt);

    // 6) em_tok + normalize
    gemm_k<<<dim3(8,1,BB),256>>>(
        emap, mmap, emtok, EE, LL, MM,
        (long long)EE*MM, (long long)MM*LL, (long long)EE*LL);
    rownorm_k<<<BB*EE, 256>>>(emtok);

    // 7) ent_att (BM=32 tile)
    gemm32_k<<<dim3(8,1,BB*HH),256>>>(emtok, attention, entatt);

    // 8) per-pair vectors
    pair_att_k<<<BB*PP, 64>>>(hts, emap, eatt, hatt, tatt);
    ctx_k<<<BB*PP, 256>>>(hts, entatt, ctxH2, ctxL2);

    // 9) h, t merged (FFMA, fp16-split epilogue)
    ht9_k<<<dim3(12,8,2*BB),256>>>(tatt, hatt, mention, hH2, hL2, tH2, tL2);

    // 10) context_info (bf16x3 NT, fp16-split out)
    bf10_k<<<dim3(12,4,BB),256,BF_SMEM>>>(ctxH2, ctxL2, ctxtH2, ctxtL2,
                                          cinfoH2, cinfoL2);

    // 11+12) fused tanh-linears (fp16 2-term)
    hf1112_k<<<dim3(12,16,2),256,HF_SMEM>>>(
        hH2, hL2, tH2, tL2, hWf, tWf,
        cinfoH2, cinfoL2, hcWf, tcWf,
        hb, tb, hcb, tcb, hf, tf);

    // 13) classifier (fp16 2-term, 2 CTAs/SM)
    clasmma_k<<<dim3(BB*PP/128, NBK, 4), 256, CLAS_SMEM>>>(hf, tf, Wt, part);
    clas_red_k<<<(BB*PP*RR + 255)/256, 256>>>(part, clasb, out);
}